// round 8
// baseline (speedup 1.0000x reference)
#include <cuda_runtime.h>
#include <cuda_bf16.h>
#include <stdint.h>
#include <math.h>

// ---------------------------------------------------------------------------
// Problem constants
// ---------------------------------------------------------------------------
#define VOCABN 32000
#define BATCH  128
#define BTN    256          // 2*BATCH
#define NTREEN 1023
#define NPRE   1280         // iou(768) | f0(256) | f1(256)

// ---------------------------------------------------------------------------
// Scratch (device globals) — h kept as separate bf16 hi/lo planes
// ---------------------------------------------------------------------------
__device__ __align__(16) __nv_bfloat16 g_emb_hi[(size_t)VOCABN * 256];
__device__ __align__(16) __nv_bfloat16 g_emb_lo[(size_t)VOCABN * 256];
__device__ __align__(16) __nv_bfloat16 g_Wt_hi[768 * 256];
__device__ __align__(16) __nv_bfloat16 g_Wt_lo[768 * 256];
__device__ __align__(16) __nv_bfloat16 g_Wc_hi[NPRE * 256];
__device__ __align__(16) __nv_bfloat16 g_Wc_lo[NPRE * 256];
__device__ __align__(16) __nv_bfloat16 g_h_hi[(size_t)BTN * NTREEN * 256];
__device__ __align__(16) __nv_bfloat16 g_h_lo[(size_t)BTN * NTREEN * 256];
__device__ __align__(16) __nv_bfloat16 g_hsum_hi[(size_t)65536 * 256];
__device__ __align__(16) __nv_bfloat16 g_hsum_lo[(size_t)65536 * 256];
__device__ __align__(16) float g_c    [(size_t)BTN * NTREEN * 256];
__device__ __align__(16) float g_pre  [(size_t)65536 * NPRE];
__device__ __align__(16) float g_table[(size_t)VOCABN * 768];

// ---------------------------------------------------------------------------
// Helpers
// ---------------------------------------------------------------------------
__device__ __forceinline__ float sigf(float x)   { return 1.0f / (1.0f + __expf(-x)); }
__device__ __forceinline__ float tanhf_(float x) { return 2.0f / (1.0f + __expf(-2.0f * x)) - 1.0f; }

__device__ __forceinline__ void split16(float x, unsigned short& hb, unsigned short& lb) {
    __nv_bfloat16 h = __float2bfloat16(x);
    float hf = __bfloat162float(h);
    __nv_bfloat16 l = __float2bfloat16(x - hf);
    hb = __bfloat16_as_ushort(h);
    lb = __bfloat16_as_ushort(l);
}

__device__ __forceinline__ uint32_t smem_u32(const void* p) {
    uint32_t a;
    asm("{ .reg .u64 t; cvta.to.shared.u64 t, %1; cvt.u32.u64 %0, t; }" : "=r"(a) : "l"(p));
    return a;
}

// ---------------------------------------------------------------------------
// Baseline-PTX tensor ops + cp.async
// ---------------------------------------------------------------------------
__device__ __forceinline__ void ldm_x4(uint32_t r[4], uint32_t addr) {
    asm volatile("ldmatrix.sync.aligned.m8n8.x4.shared.b16 {%0,%1,%2,%3}, [%4];"
        : "=r"(r[0]), "=r"(r[1]), "=r"(r[2]), "=r"(r[3]) : "r"(addr));
}
__device__ __forceinline__ void ldm_x2(uint32_t r[2], uint32_t addr) {
    asm volatile("ldmatrix.sync.aligned.m8n8.x2.shared.b16 {%0,%1}, [%2];"
        : "=r"(r[0]), "=r"(r[1]) : "r"(addr));
}
__device__ __forceinline__ void mma_bf16(float c[4], const uint32_t a[4], const uint32_t b[2]) {
    asm volatile("mma.sync.aligned.m16n8k16.row.col.f32.bf16.bf16.f32 "
        "{%0,%1,%2,%3}, {%4,%5,%6,%7}, {%8,%9}, {%0,%1,%2,%3};"
        : "+f"(c[0]), "+f"(c[1]), "+f"(c[2]), "+f"(c[3])
        : "r"(a[0]), "r"(a[1]), "r"(a[2]), "r"(a[3]), "r"(b[0]), "r"(b[1]));
}
#define CP16(dst, src) asm volatile("cp.async.cg.shared.global [%0], [%1], 16;" :: "r"(dst), "l"(src))
#define CP_COMMIT()    asm volatile("cp.async.commit_group;" ::: "memory")
#define CP_WAIT1()     asm volatile("cp.async.wait_group 1;" ::: "memory")
#define CP_WAIT0()     asm volatile("cp.async.wait_group 0;" ::: "memory")

// ---------------------------------------------------------------------------
// Prep kernels (device globals referenced from device code only)
// ---------------------------------------------------------------------------
__global__ __launch_bounds__(256) void split_emb(const float* __restrict__ src)
{
    const int idx = blockIdx.x * 256 + threadIdx.x;
    unsigned short h, l;
    split16(src[idx], h, l);
    g_emb_hi[idx] = __ushort_as_bfloat16(h);
    g_emb_lo[idx] = __ushort_as_bfloat16(l);
}

__global__ __launch_bounds__(256) void split_wt(const float* __restrict__ src)
{
    const int idx = blockIdx.x * 256 + threadIdx.x;
    unsigned short h, l;
    split16(src[idx], h, l);
    g_Wt_hi[idx] = __ushort_as_bfloat16(h);
    g_Wt_lo[idx] = __ushort_as_bfloat16(l);
}

// Wc rows: [0:768)=U_iou, [768:1024)=U_f_w, [1024:1280)=U_f_w
__global__ __launch_bounds__(256) void build_wc(
    const float* __restrict__ U_iou, const float* __restrict__ U_f_w)
{
    const int idx = blockIdx.x * 256 + threadIdx.x;
    const int n = idx >> 8, k = idx & 255;
    const float v = (n < 768) ? U_iou[n * 256 + k]
                              : U_f_w[((n - 768) & 255) * 256 + k];
    unsigned short h, l;
    split16(v, h, l);
    g_Wc_hi[idx] = __ushort_as_bfloat16(h);
    g_Wc_lo[idx] = __ushort_as_bfloat16(l);
}

// ---------------------------------------------------------------------------
// Double-buffered bf16 hi/lo GEMM.  C[M,N] = A[M,256] @ B[N,256]^T  (fp32)
// CTA tile 128x128; K = 8 chunks of 32; 2-stage cp.async pipeline.
// smem row layout (128B): [hi 32 cols (64B) | lo 32 cols (64B)] per chunk.
// Stage = A 16K + B 16K = 32K; 2 stages = 64K; 2 CTAs/SM.
// MODE 0: A = emb planes, B = Wt,  C = g_table (Nc=768, 6 n-tiles)
// MODE 1: tiles 0-5: A = hsum | tiles 6,7: A = child0 | 8,9: child1
//         B = Wc, C = g_pre (Nc=1280)
// ---------------------------------------------------------------------------
#define SM_A 0u
#define SM_B 16384u
#define STGS 32768u
#define SMT  65536

template<int MODE>
__global__ __launch_bounds__(256, 2) void gemm_f(int base)
{
    extern __shared__ char smem[];
    const uint32_t sb = smem_u32(smem);
    const int tid = threadIdx.x, wid = tid >> 5, lane = tid & 31;
    const int bm = blockIdx.x * 128;
    const int tile = blockIdx.y;
    const int bn = tile * 128;
    const int Nc = (MODE == 0) ? 768 : NPRE;

    // A plane row pointer (row = tid>>1; tid&1 selects hi(0)/lo(1) plane)
    const __nv_bfloat16* asrc;
    {
        const int r = bm + (tid >> 1);
        const __nv_bfloat16 *ahi, *alo;
        if (MODE == 0) {
            ahi = g_emb_hi + (size_t)r * 256;
            alo = g_emb_lo + (size_t)r * 256;
        } else if (tile < 6) {
            ahi = g_hsum_hi + (size_t)r * 256;
            alo = g_hsum_lo + (size_t)r * 256;
        } else {
            const int s = (tile - 6) >> 1;
            const int j = r >> 8, bt = r & 255, node = base + j;
            const size_t off = ((size_t)bt * NTREEN + 2 * node + 1 + s) * 256;
            ahi = g_h_hi + off;
            alo = g_h_lo + off;
        }
        asrc = (tid & 1) ? alo : ahi;
    }
    const __nv_bfloat16* bsrc =
        ((tid & 1) ? ((MODE == 0) ? g_Wt_lo : g_Wc_lo)
                   : ((MODE == 0) ? g_Wt_hi : g_Wc_hi))
        + (size_t)(bn + (tid >> 1)) * 256;

    const uint32_t row  = (uint32_t)(tid >> 1);
    const uint32_t rx   = (row & 7u) << 4;
    const uint32_t xb0  = (uint32_t)(tid & 1) * 64u;   // hi->0, lo->64

    #define LOADC(s, k0) do {                                                  \
        const uint32_t st_ = sb + (uint32_t)(s) * STGS;                        \
        _Pragma("unroll")                                                      \
        for (int j = 0; j < 4; j++) {                                          \
            const uint32_t off = row * 128u + ((xb0 + j * 16u) ^ rx);          \
            CP16(st_ + SM_A + off, asrc + (k0) + j * 8);                       \
            CP16(st_ + SM_B + off, bsrc + (k0) + j * 8);                       \
        }                                                                      \
    } while (0)

    const int wm = (wid & 1) * 64;
    const int wn = (wid >> 1) * 32;
    float acc[4][4][4] = {};

    LOADC(0, 0);
    CP_COMMIT();

    #pragma unroll 1
    for (int kc = 0; kc < 8; kc++) {
        if (kc < 7) {
            LOADC((kc + 1) & 1, (kc + 1) * 32);
            CP_COMMIT();
            CP_WAIT1();
        } else {
            CP_WAIT0();
        }
        __syncthreads();

        const uint32_t st = sb + (uint32_t)(kc & 1) * STGS;
        #pragma unroll
        for (int kg = 0; kg < 2; kg++) {
            uint32_t bh[4][2], bl[4][2];
            #pragma unroll
            for (int nf = 0; nf < 4; nf++) {
                const uint32_t nrow = (uint32_t)(wn + nf * 8 + (lane & 7));
                const uint32_t nx = (uint32_t)(kg * 32 + ((lane >> 3) & 1) * 16);
                const uint32_t nr = nrow * 128u;
                const uint32_t nxr = (nrow & 7u) << 4;
                ldm_x2(bh[nf], st + SM_B + nr + (nx ^ nxr));
                ldm_x2(bl[nf], st + SM_B + nr + ((nx + 64u) ^ nxr));
            }
            #pragma unroll
            for (int mf = 0; mf < 4; mf++) {
                const uint32_t mrow = (uint32_t)(wm + mf * 16 + (lane & 15));
                const uint32_t mx = (uint32_t)(kg * 32 + (lane >> 4) * 16);
                const uint32_t mr = mrow * 128u;
                const uint32_t mxr = (mrow & 7u) << 4;
                uint32_t a[4];
                ldm_x4(a, st + SM_A + mr + (mx ^ mxr));        // A hi
                #pragma unroll
                for (int nf = 0; nf < 4; nf++) {
                    mma_bf16(acc[mf][nf], a, bh[nf]);          // hh
                    mma_bf16(acc[mf][nf], a, bl[nf]);          // hl
                }
                ldm_x4(a, st + SM_A + mr + ((mx + 64u) ^ mxr)); // A lo
                #pragma unroll
                for (int nf = 0; nf < 4; nf++)
                    mma_bf16(acc[mf][nf], a, bh[nf]);          // lh
            }
        }
        __syncthreads();
    }
    #undef LOADC

    // ---- epilogue ----
    float* __restrict__ C = (MODE == 0) ? g_table : g_pre;
    #pragma unroll
    for (int mf = 0; mf < 4; mf++) {
        const int crow = bm + wm + mf * 16 + (lane >> 2);
        #pragma unroll
        for (int nf = 0; nf < 4; nf++) {
            const int col = bn + wn + nf * 8 + (lane & 3) * 2;
            *(float2*)&C[(size_t)crow * Nc + col] =
                make_float2(acc[mf][nf][0], acc[mf][nf][1]);
            *(float2*)&C[(size_t)(crow + 8) * Nc + col] =
                make_float2(acc[mf][nf][2], acc[mf][nf][3]);
        }
    }
}

// ---------------------------------------------------------------------------
// h store helper: split 4 fp32 -> hi/lo planes
// ---------------------------------------------------------------------------
__device__ __forceinline__ void store_h4(size_t rowoff, int hs4, const float h[4]) {
    unsigned short hb[4], lb[4];
    #pragma unroll
    for (int e = 0; e < 4; e++) split16(h[e], hb[e], lb[e]);
    ((uint2*)(g_h_hi + rowoff))[hs4] =
        make_uint2(hb[0] | ((unsigned)hb[1] << 16), hb[2] | ((unsigned)hb[3] << 16));
    ((uint2*)(g_h_lo + rowoff))[hs4] =
        make_uint2(lb[0] | ((unsigned)lb[1] << 16), lb[2] | ((unsigned)lb[3] << 16));
}

__device__ __forceinline__ void store_hsum4(size_t rowoff, int hs4, const float h[4]) {
    unsigned short hb[4], lb[4];
    #pragma unroll
    for (int e = 0; e < 4; e++) split16(h[e], hb[e], lb[e]);
    ((uint2*)(g_hsum_hi + rowoff))[hs4] =
        make_uint2(hb[0] | ((unsigned)hb[1] << 16), hb[2] | ((unsigned)hb[3] << 16));
    ((uint2*)(g_hsum_lo + rowoff))[hs4] =
        make_uint2(lb[0] | ((unsigned)lb[1] << 16), lb[2] | ((unsigned)lb[3] << 16));
}

// ---------------------------------------------------------------------------
// Leaf elementwise, fused sibling pair + hsum.
// Thread handles pair tp for batch bt: leaves 511+2tp, 511+2tp+1.
// ---------------------------------------------------------------------------
__global__ __launch_bounds__(256) void leaf_ew_pair(
    const int* __restrict__ types1, const int* __restrict__ types2,
    const float* __restrict__ b_iou)
{
    const int tid = blockIdx.x * 256 + threadIdx.x;
    const int hs4 = tid & 63;
    const int q   = tid >> 6;            // 0 .. 256*256-1
    const int bt  = q & 255;
    const int tp  = q >> 8;              // pair 0..255

    const int* ty = (bt < BATCH) ? types1 + bt * NTREEN
                                 : types2 + (bt - BATCH) * NTREEN;
    const float4* bb = (const float4*)b_iou;
    const float4 b0 = bb[hs4], b1 = bb[64 + hs4], b2 = bb[128 + hs4];

    float hsum[4] = {0.f, 0.f, 0.f, 0.f};
    #pragma unroll
    for (int s = 0; s < 2; s++) {
        const int node = 511 + 2 * tp + s;
        const int v = ty[node];
        const float4* t = (const float4*)(g_table + (size_t)v * 768);
        const float4 i4 = t[hs4], o4 = t[64 + hs4], u4 = t[128 + hs4];

        float4 cn; float hv[4];
        #define DOLANE(c_, e_)                                       \
        {   float cv = sigf(i4.c_ + b0.c_) * tanhf_(u4.c_ + b2.c_);  \
            cn.c_ = cv;                                              \
            hv[e_] = sigf(o4.c_ + b1.c_) * tanhf_(cv);               \
            hsum[e_] += hv[e_]; }
        DOLANE(x, 0) DOLANE(y, 1) DOLANE(z, 2) DOLANE(w, 3)
        #undef DOLANE

        const size_t rowoff = ((size_t)bt * NTREEN + node) * 256;
        ((float4*)(g_c + rowoff))[hs4] = cn;
        store_h4(rowoff, hs4, hv);
    }
    store_hsum4((size_t)(tp * 256 + bt) * 256, hs4, hsum);
}

// ---------------------------------------------------------------------------
// Internal-level elementwise, fused sibling pair + hsum.
// cbase = base of the level whose nodes we compute; pairs 2tp, 2tp+1.
// ---------------------------------------------------------------------------
__global__ __launch_bounds__(256) void level_ew_pair(
    const float* __restrict__ b_iou, const float* __restrict__ U_f_b, int cbase)
{
    const int tid = blockIdx.x * 256 + threadIdx.x;
    const int hs4 = tid & 63;
    const int q   = tid >> 6;
    const int bt  = q & 255;
    const int tp  = q >> 8;

    const float4* bb = (const float4*)b_iou;
    const float4 b0 = bb[hs4], b1 = bb[64 + hs4], b2 = bb[128 + hs4];
    const float4 fb = ((const float4*)U_f_b)[hs4];

    float hsum[4] = {0.f, 0.f, 0.f, 0.f};
    #pragma unroll
    for (int s = 0; s < 2; s++) {
        const int node = cbase + 2 * tp + s;
        const int i    = (2 * tp + s) * 256 + bt;

        const size_t rc0 = ((size_t)bt * NTREEN + 2 * node + 1) * 256;
        const float4 c0 = ((const float4*)(g_c + rc0))[hs4];
        const float4 c1 = ((const float4*)(g_c + rc0 + 256))[hs4];

        const float4* pre = (const float4*)(g_pre + (size_t)i * NPRE);
        const float4 iI = pre[hs4], iO = pre[64 + hs4], iU = pre[128 + hs4];
        const float4 f0 = pre[192 + hs4], f1 = pre[256 + hs4];

        float4 cn; float hv[4];
        #define DOLANE(c_, e_)                                                      \
        {   float csum = sigf(f0.c_ + fb.c_) * c0.c_ + sigf(f1.c_ + fb.c_) * c1.c_; \
            float cv = sigf(iI.c_ + b0.c_) * tanhf_(iU.c_ + b2.c_) + csum;          \
            cn.c_ = cv;                                                             \
            hv[e_] = sigf(iO.c_ + b1.c_) * tanhf_(cv);                              \
            hsum[e_] += hv[e_]; }
        DOLANE(x, 0) DOLANE(y, 1) DOLANE(z, 2) DOLANE(w, 3)
        #undef DOLANE

        const size_t rowoff = ((size_t)bt * NTREEN + node) * 256;
        ((float4*)(g_c + rowoff))[hs4] = cn;
        store_h4(rowoff, hs4, hv);
    }
    store_hsum4((size_t)(tp * 256 + bt) * 256, hs4, hsum);
}

// ---------------------------------------------------------------------------
// Root elementwise (node 0, no hsum)
// ---------------------------------------------------------------------------
__global__ __launch_bounds__(256) void level_ew_root(
    const float* __restrict__ b_iou, const float* __restrict__ U_f_b)
{
    const int tid = blockIdx.x * 256 + threadIdx.x;
    const int hs4 = tid & 63;
    const int bt  = tid >> 6;            // 0..255

    const size_t rc0 = ((size_t)bt * NTREEN + 1) * 256;
    const float4 c0 = ((const float4*)(g_c + rc0))[hs4];
    const float4 c1 = ((const float4*)(g_c + rc0 + 256))[hs4];

    const float4* pre = (const float4*)(g_pre + (size_t)bt * NPRE);
    const float4 iI = pre[hs4], iO = pre[64 + hs4], iU = pre[128 + hs4];
    const float4 f0 = pre[192 + hs4], f1 = pre[256 + hs4];

    const float4* bb = (const float4*)b_iou;
    const float4 b0 = bb[hs4], b1 = bb[64 + hs4], b2 = bb[128 + hs4];
    const float4 fb = ((const float4*)U_f_b)[hs4];

    float4 cn; float hv[4];
    #define DOLANE(c_, e_)                                                      \
    {   float csum = sigf(f0.c_ + fb.c_) * c0.c_ + sigf(f1.c_ + fb.c_) * c1.c_; \
        float cv = sigf(iI.c_ + b0.c_) * tanhf_(iU.c_ + b2.c_) + csum;          \
        cn.c_ = cv;                                                             \
        hv[e_] = sigf(iO.c_ + b1.c_) * tanhf_(cv); }
    DOLANE(x, 0) DOLANE(y, 1) DOLANE(z, 2) DOLANE(w, 3)
    #undef DOLANE

    const size_t rowoff = (size_t)bt * NTREEN * 256;
    ((float4*)(g_c + rowoff))[hs4] = cn;
    store_h4(rowoff, hs4, hv);
}

// ---------------------------------------------------------------------------
// Final classifier
// ---------------------------------------------------------------------------
__global__ __launch_bounds__(256) void final_k(
    const float* __restrict__ cls_w, const float* __restrict__ cls_b,
    float* __restrict__ out)
{
    const int b  = blockIdx.x;
    const int hs = threadIdx.x;

    const size_t o1 = (size_t)b           * NTREEN * 256 + hs;
    const size_t o2 = (size_t)(b + BATCH) * NTREEN * 256 + hs;

    float s1 = 0.f, s2 = 0.f;
    #pragma unroll 4
    for (int n = 0; n < NTREEN; n++) {
        s1 += __bfloat162float(g_h_hi[o1 + (size_t)n * 256])
            + __bfloat162float(g_h_lo[o1 + (size_t)n * 256]);
        s2 += __bfloat162float(g_h_hi[o2 + (size_t)n * 256])
            + __bfloat162float(g_h_lo[o2 + (size_t)n * 256]);
    }
    const float d = fabsf(s1 - s2) * (1.0f / (float)NTREEN);

    float v0 = d * cls_w[hs];
    float v1 = d * cls_w[256 + hs];

    #pragma unroll
    for (int off = 16; off > 0; off >>= 1) {
        v0 += __shfl_down_sync(0xffffffffu, v0, off);
        v1 += __shfl_down_sync(0xffffffffu, v1, off);
    }
    __shared__ float sm0[8], sm1[8];
    const int w = threadIdx.x >> 5, lane = threadIdx.x & 31;
    if (lane == 0) { sm0[w] = v0; sm1[w] = v1; }
    __syncthreads();
    if (threadIdx.x == 0) {
        float t0 = 0.f, t1 = 0.f;
        #pragma unroll
        for (int k = 0; k < 8; k++) { t0 += sm0[k]; t1 += sm1[k]; }
        out[b * 2 + 0] = t0 + cls_b[0];
        out[b * 2 + 1] = t1 + cls_b[1];
    }
}

// ---------------------------------------------------------------------------
// Launch
// ---------------------------------------------------------------------------
extern "C" void kernel_launch(void* const* d_in, const int* in_sizes, int n_in,
                              void* d_out, int out_size)
{
    (void)in_sizes; (void)n_in; (void)out_size;
    const int*   types1 = (const int*)  d_in[0];
    const int*   types2 = (const int*)  d_in[1];
    const float* emb    = (const float*)d_in[2];
    const float* W_iou  = (const float*)d_in[3];
    const float* U_iou  = (const float*)d_in[4];
    const float* b_iou  = (const float*)d_in[5];
    const float* U_f_w  = (const float*)d_in[6];
    const float* U_f_b  = (const float*)d_in[7];
    const float* cls_w  = (const float*)d_in[8];
    const float* cls_b  = (const float*)d_in[9];
    float* out = (float*)d_out;

    cudaFuncSetAttribute(gemm_f<0>, cudaFuncAttributeMaxDynamicSharedMemorySize, SMT);
    cudaFuncSetAttribute(gemm_f<1>, cudaFuncAttributeMaxDynamicSharedMemorySize, SMT);

    // 0) prep: split emb + weights into bf16 hi/lo planes
    split_emb<<<VOCABN, 256>>>(emb);
    split_wt<<<768, 256>>>(W_iou);
    build_wc<<<NPRE, 256>>>(U_iou, U_f_w);

    // 1) vocab table: g_table[v] = W_iou @ emb[v]
    gemm_f<0><<<dim3(VOCABN / 128, 6), 256, SMT>>>(0);

    // 2) leaves (+ hsum for level 8)
    leaf_ew_pair<<<16384, 256>>>(types1, types2, b_iou);

    // 3) internal levels 8..1 (GEMM -> fused ew+hsum)
    for (int lvl = 8; lvl >= 1; --lvl) {
        const int base = (1 << lvl) - 1;
        gemm_f<1><<<dim3((BTN << lvl) / 128, 10), 256, SMT>>>(base);
        level_ew_pair<<<64 << (lvl - 1), 256>>>(b_iou, U_f_b, base);
    }

    // 4) root level
    gemm_f<1><<<dim3(2, 10), 256, SMT>>>(0);
    level_ew_root<<<64, 256>>>(b_iou, U_f_b);

    // 5) classifier
    final_k<<<BATCH, 256>>>(cls_w, cls_b, out);
}

// round 9
// speedup vs baseline: 1.2026x; 1.2026x over previous
#include <cuda_runtime.h>
#include <cuda_bf16.h>
#include <stdint.h>
#include <math.h>

// ---------------------------------------------------------------------------
// Problem constants
// ---------------------------------------------------------------------------
#define VOCABN 32000
#define BATCH  128
#define BTN    256          // 2*BATCH
#define NTREEN 1023
#define NPRE   1280         // iou(768) | f0(256) | f1(256)

// ---------------------------------------------------------------------------
// Scratch (device globals) — h kept as separate bf16 hi/lo planes
// ---------------------------------------------------------------------------
__device__ __align__(16) __nv_bfloat16 g_emb_hi[(size_t)VOCABN * 256];
__device__ __align__(16) __nv_bfloat16 g_emb_lo[(size_t)VOCABN * 256];
__device__ __align__(16) __nv_bfloat16 g_Wt_hi[768 * 256];
__device__ __align__(16) __nv_bfloat16 g_Wt_lo[768 * 256];
__device__ __align__(16) __nv_bfloat16 g_Wc_hi[NPRE * 256];
__device__ __align__(16) __nv_bfloat16 g_Wc_lo[NPRE * 256];
__device__ __align__(16) __nv_bfloat16 g_h_hi[(size_t)BTN * NTREEN * 256];
__device__ __align__(16) __nv_bfloat16 g_h_lo[(size_t)BTN * NTREEN * 256];
__device__ __align__(16) __nv_bfloat16 g_hsum_hi[(size_t)65536 * 256];
__device__ __align__(16) __nv_bfloat16 g_hsum_lo[(size_t)65536 * 256];
__device__ __align__(16) float g_c    [(size_t)BTN * NTREEN * 256];
__device__ __align__(16) float g_pre  [(size_t)65536 * NPRE];
__device__ __align__(16) float g_table[(size_t)VOCABN * 768];

// ---------------------------------------------------------------------------
// Helpers
// ---------------------------------------------------------------------------
__device__ __forceinline__ float sigf(float x)   { return 1.0f / (1.0f + __expf(-x)); }
__device__ __forceinline__ float tanhf_(float x) { return 2.0f / (1.0f + __expf(-2.0f * x)) - 1.0f; }

__device__ __forceinline__ void split16(float x, unsigned short& hb, unsigned short& lb) {
    __nv_bfloat16 h = __float2bfloat16(x);
    float hf = __bfloat162float(h);
    __nv_bfloat16 l = __float2bfloat16(x - hf);
    hb = __bfloat16_as_ushort(h);
    lb = __bfloat16_as_ushort(l);
}

__device__ __forceinline__ uint32_t smem_u32(const void* p) {
    uint32_t a;
    asm("{ .reg .u64 t; cvta.to.shared.u64 t, %1; cvt.u32.u64 %0, t; }" : "=r"(a) : "l"(p));
    return a;
}

// ---------------------------------------------------------------------------
// Baseline-PTX tensor ops + cp.async
// ---------------------------------------------------------------------------
__device__ __forceinline__ void ldm_x4(uint32_t r[4], uint32_t addr) {
    asm volatile("ldmatrix.sync.aligned.m8n8.x4.shared.b16 {%0,%1,%2,%3}, [%4];"
        : "=r"(r[0]), "=r"(r[1]), "=r"(r[2]), "=r"(r[3]) : "r"(addr));
}
__device__ __forceinline__ void ldm_x2(uint32_t r[2], uint32_t addr) {
    asm volatile("ldmatrix.sync.aligned.m8n8.x2.shared.b16 {%0,%1}, [%2];"
        : "=r"(r[0]), "=r"(r[1]) : "r"(addr));
}
__device__ __forceinline__ void mma_bf16(float c[4], const uint32_t a[4], const uint32_t b[2]) {
    asm volatile("mma.sync.aligned.m16n8k16.row.col.f32.bf16.bf16.f32 "
        "{%0,%1,%2,%3}, {%4,%5,%6,%7}, {%8,%9}, {%0,%1,%2,%3};"
        : "+f"(c[0]), "+f"(c[1]), "+f"(c[2]), "+f"(c[3])
        : "r"(a[0]), "r"(a[1]), "r"(a[2]), "r"(a[3]), "r"(b[0]), "r"(b[1]));
}
#define CP16(dst, src) asm volatile("cp.async.cg.shared.global [%0], [%1], 16;" :: "r"(dst), "l"(src))
#define CP_COMMIT()    asm volatile("cp.async.commit_group;" ::: "memory")
#define CP_WAIT0()     asm volatile("cp.async.wait_group 0;" ::: "memory")

// ---------------------------------------------------------------------------
// Prep kernels (device globals referenced from device code only)
// ---------------------------------------------------------------------------
__global__ __launch_bounds__(256) void split_emb(const float* __restrict__ src)
{
    const int idx = blockIdx.x * 256 + threadIdx.x;
    unsigned short h, l;
    split16(src[idx], h, l);
    g_emb_hi[idx] = __ushort_as_bfloat16(h);
    g_emb_lo[idx] = __ushort_as_bfloat16(l);
}

__global__ __launch_bounds__(256) void split_wt(const float* __restrict__ src)
{
    const int idx = blockIdx.x * 256 + threadIdx.x;
    unsigned short h, l;
    split16(src[idx], h, l);
    g_Wt_hi[idx] = __ushort_as_bfloat16(h);
    g_Wt_lo[idx] = __ushort_as_bfloat16(l);
}

// Wc rows: [0:768)=U_iou, [768:1024)=U_f_w, [1024:1280)=U_f_w
__global__ __launch_bounds__(256) void build_wc(
    const float* __restrict__ U_iou, const float* __restrict__ U_f_w)
{
    const int idx = blockIdx.x * 256 + threadIdx.x;
    const int n = idx >> 8, k = idx & 255;
    const float v = (n < 768) ? U_iou[n * 256 + k]
                              : U_f_w[((n - 768) & 255) * 256 + k];
    unsigned short h, l;
    split16(v, h, l);
    g_Wc_hi[idx] = __ushort_as_bfloat16(h);
    g_Wc_lo[idx] = __ushort_as_bfloat16(l);
}

// ---------------------------------------------------------------------------
// bf16 hi/lo GEMM via mma.sync + cp.async (ROUND-7 PROVEN CONFIG).
// C[M,N] = A[M,256] @ B[N,256]^T.  CTA tile 128x128; K = 4 chunks of 64;
// single 64KB stage (AH|AL|BH|BL 16K each), 2 CTAs/SM for overlap.
// MODE 0: A = emb planes, B = Wt,  C = g_table (Nc=768, 6 n-tiles)
// MODE 1: tiles 0-5: A = hsum | tiles 6,7: A = child0 | 8,9: child1
//         B = Wc, C = g_pre (Nc=1280)
// ---------------------------------------------------------------------------
#define SM_AH 0u
#define SM_AL 16384u
#define SM_BH 32768u
#define SM_BL 49152u
#define SMT   65536

template<int MODE>
__global__ __launch_bounds__(256, 2) void gemm_f(int base)
{
    extern __shared__ char smem[];
    const uint32_t sb = smem_u32(smem);
    const int tid = threadIdx.x, wid = tid >> 5, lane = tid & 31;
    const int bm = blockIdx.x * 128;
    const int tile = blockIdx.y;
    const int bn = tile * 128;
    const int Nc = (MODE == 0) ? 768 : NPRE;

    // A source row pointer (row = tid>>1, half = tid&1 -> 32 elems)
    const __nv_bfloat16 *ahi, *alo;
    {
        const int r = bm + (tid >> 1);
        if (MODE == 0) {
            ahi = g_emb_hi + (size_t)r * 256;
            alo = g_emb_lo + (size_t)r * 256;
        } else if (tile < 6) {
            ahi = g_hsum_hi + (size_t)r * 256;
            alo = g_hsum_lo + (size_t)r * 256;
        } else {
            const int s = (tile - 6) >> 1;
            const int j = r >> 8, bt = r & 255, node = base + j;
            const size_t off = ((size_t)bt * NTREEN + 2 * node + 1 + s) * 256;
            ahi = g_h_hi + off;
            alo = g_h_lo + off;
        }
        ahi += (tid & 1) * 32;
        alo += (tid & 1) * 32;
    }
    // B source row pointer (row = tid>>1, half = tid&1)
    const __nv_bfloat16* bhi = ((MODE == 0) ? g_Wt_hi : g_Wc_hi)
                               + (size_t)(bn + (tid >> 1)) * 256 + (tid & 1) * 32;
    const __nv_bfloat16* blo = ((MODE == 0) ? g_Wt_lo : g_Wc_lo)
                               + (size_t)(bn + (tid >> 1)) * 256 + (tid & 1) * 32;

    const uint32_t rowoff = (uint32_t)(tid >> 1) * 128u;
    const uint32_t rxor   = (uint32_t)(((tid >> 1) & 7) << 4);

    const int wm = (wid & 1) * 64;
    const int wn = (wid >> 1) * 32;
    float acc[4][4][4] = {};

    #pragma unroll 1
    for (int kc = 0; kc < 4; kc++) {
        const int k0 = kc * 64;

        // ---- async loads: 16 x 16B per thread ----
        #pragma unroll
        for (int j = 0; j < 4; j++) {
            const uint32_t xo = (uint32_t)((tid & 1) * 64 + j * 16) ^ rxor;
            const uint32_t d = rowoff + xo;
            CP16(sb + SM_AH + d, ahi + k0 + j * 8);
            CP16(sb + SM_AL + d, alo + k0 + j * 8);
            CP16(sb + SM_BH + d, bhi + k0 + j * 8);
            CP16(sb + SM_BL + d, blo + k0 + j * 8);
        }
        CP_COMMIT();
        CP_WAIT0();
        __syncthreads();

        // ---- compute: 4 k16-groups, 3 passes (hh, hl, lh) ----
        #pragma unroll
        for (int kg = 0; kg < 4; kg++) {
            uint32_t bh[4][2], bl[4][2];
            #pragma unroll
            for (int nf = 0; nf < 4; nf++) {
                const uint32_t nrow = (uint32_t)(wn + nf * 8 + (lane & 7));
                const uint32_t x = (uint32_t)(kg * 32 + ((lane >> 3) & 1) * 16);
                const uint32_t sw = nrow * 128u + (x ^ ((nrow & 7u) << 4));
                ldm_x2(bh[nf], sb + SM_BH + sw);
                ldm_x2(bl[nf], sb + SM_BL + sw);
            }
            #pragma unroll
            for (int mf = 0; mf < 4; mf++) {
                const uint32_t mrow = (uint32_t)(wm + mf * 16 + (lane & 15));
                const uint32_t x = (uint32_t)(kg * 32 + (lane >> 4) * 16);
                const uint32_t sw = mrow * 128u + (x ^ ((mrow & 7u) << 4));
                uint32_t a[4];
                ldm_x4(a, sb + SM_AH + sw);       // A hi
                #pragma unroll
                for (int nf = 0; nf < 4; nf++) {
                    mma_bf16(acc[mf][nf], a, bh[nf]);   // hh
                    mma_bf16(acc[mf][nf], a, bl[nf]);   // hl
                }
                ldm_x4(a, sb + SM_AL + sw);       // A lo
                #pragma unroll
                for (int nf = 0; nf < 4; nf++)
                    mma_bf16(acc[mf][nf], a, bh[nf]);   // lh
            }
        }
        __syncthreads();
    }

    // ---- epilogue ----
    float* __restrict__ C = (MODE == 0) ? g_table : g_pre;
    #pragma unroll
    for (int mf = 0; mf < 4; mf++) {
        const int row = bm + wm + mf * 16 + (lane >> 2);
        #pragma unroll
        for (int nf = 0; nf < 4; nf++) {
            const int col = bn + wn + nf * 8 + (lane & 3) * 2;
            *(float2*)&C[(size_t)row * Nc + col] =
                make_float2(acc[mf][nf][0], acc[mf][nf][1]);
            *(float2*)&C[(size_t)(row + 8) * Nc + col] =
                make_float2(acc[mf][nf][2], acc[mf][nf][3]);
        }
    }
}

// ---------------------------------------------------------------------------
// h store helpers: split 4 fp32 -> hi/lo planes
// ---------------------------------------------------------------------------
__device__ __forceinline__ void store_h4(size_t rowoff, int hs4, const float h[4]) {
    unsigned short hb[4], lb[4];
    #pragma unroll
    for (int e = 0; e < 4; e++) split16(h[e], hb[e], lb[e]);
    ((uint2*)(g_h_hi + rowoff))[hs4] =
        make_uint2(hb[0] | ((unsigned)hb[1] << 16), hb[2] | ((unsigned)hb[3] << 16));
    ((uint2*)(g_h_lo + rowoff))[hs4] =
        make_uint2(lb[0] | ((unsigned)lb[1] << 16), lb[2] | ((unsigned)lb[3] << 16));
}

__device__ __forceinline__ void store_hsum4(size_t rowoff, int hs4, const float h[4]) {
    unsigned short hb[4], lb[4];
    #pragma unroll
    for (int e = 0; e < 4; e++) split16(h[e], hb[e], lb[e]);
    ((uint2*)(g_hsum_hi + rowoff))[hs4] =
        make_uint2(hb[0] | ((unsigned)hb[1] << 16), hb[2] | ((unsigned)hb[3] << 16));
    ((uint2*)(g_hsum_lo + rowoff))[hs4] =
        make_uint2(lb[0] | ((unsigned)lb[1] << 16), lb[2] | ((unsigned)lb[3] << 16));
}

// ---------------------------------------------------------------------------
// Leaf elementwise, fused sibling pair + hsum.
// ---------------------------------------------------------------------------
__global__ __launch_bounds__(256) void leaf_ew_pair(
    const int* __restrict__ types1, const int* __restrict__ types2,
    const float* __restrict__ b_iou)
{
    const int tid = blockIdx.x * 256 + threadIdx.x;
    const int hs4 = tid & 63;
    const int q   = tid >> 6;            // 0 .. 256*256-1
    const int bt  = q & 255;
    const int tp  = q >> 8;              // pair 0..255

    const int* ty = (bt < BATCH) ? types1 + bt * NTREEN
                                 : types2 + (bt - BATCH) * NTREEN;
    const float4* bb = (const float4*)b_iou;
    const float4 b0 = bb[hs4], b1 = bb[64 + hs4], b2 = bb[128 + hs4];

    float hsum[4] = {0.f, 0.f, 0.f, 0.f};
    #pragma unroll
    for (int s = 0; s < 2; s++) {
        const int node = 511 + 2 * tp + s;
        const int v = ty[node];
        const float4* t = (const float4*)(g_table + (size_t)v * 768);
        const float4 i4 = t[hs4], o4 = t[64 + hs4], u4 = t[128 + hs4];

        float4 cn; float hv[4];
        #define DOLANE(c_, e_)                                       \
        {   float cv = sigf(i4.c_ + b0.c_) * tanhf_(u4.c_ + b2.c_);  \
            cn.c_ = cv;                                              \
            hv[e_] = sigf(o4.c_ + b1.c_) * tanhf_(cv);               \
            hsum[e_] += hv[e_]; }
        DOLANE(x, 0) DOLANE(y, 1) DOLANE(z, 2) DOLANE(w, 3)
        #undef DOLANE

        const size_t rowoff = ((size_t)bt * NTREEN + node) * 256;
        ((float4*)(g_c + rowoff))[hs4] = cn;
        store_h4(rowoff, hs4, hv);
    }
    store_hsum4((size_t)(tp * 256 + bt) * 256, hs4, hsum);
}

// ---------------------------------------------------------------------------
// Internal-level elementwise, fused sibling pair + hsum.
// ---------------------------------------------------------------------------
__global__ __launch_bounds__(256) void level_ew_pair(
    const float* __restrict__ b_iou, const float* __restrict__ U_f_b, int cbase)
{
    const int tid = blockIdx.x * 256 + threadIdx.x;
    const int hs4 = tid & 63;
    const int q   = tid >> 6;
    const int bt  = q & 255;
    const int tp  = q >> 8;

    const float4* bb = (const float4*)b_iou;
    const float4 b0 = bb[hs4], b1 = bb[64 + hs4], b2 = bb[128 + hs4];
    const float4 fb = ((const float4*)U_f_b)[hs4];

    float hsum[4] = {0.f, 0.f, 0.f, 0.f};
    #pragma unroll
    for (int s = 0; s < 2; s++) {
        const int node = cbase + 2 * tp + s;
        const int i    = (2 * tp + s) * 256 + bt;

        const size_t rc0 = ((size_t)bt * NTREEN + 2 * node + 1) * 256;
        const float4 c0 = ((const float4*)(g_c + rc0))[hs4];
        const float4 c1 = ((const float4*)(g_c + rc0 + 256))[hs4];

        const float4* pre = (const float4*)(g_pre + (size_t)i * NPRE);
        const float4 iI = pre[hs4], iO = pre[64 + hs4], iU = pre[128 + hs4];
        const float4 f0 = pre[192 + hs4], f1 = pre[256 + hs4];

        float4 cn; float hv[4];
        #define DOLANE(c_, e_)                                                      \
        {   float csum = sigf(f0.c_ + fb.c_) * c0.c_ + sigf(f1.c_ + fb.c_) * c1.c_; \
            float cv = sigf(iI.c_ + b0.c_) * tanhf_(iU.c_ + b2.c_) + csum;          \
            cn.c_ = cv;                                                             \
            hv[e_] = sigf(iO.c_ + b1.c_) * tanhf_(cv);                              \
            hsum[e_] += hv[e_]; }
        DOLANE(x, 0) DOLANE(y, 1) DOLANE(z, 2) DOLANE(w, 3)
        #undef DOLANE

        const size_t rowoff = ((size_t)bt * NTREEN + node) * 256;
        ((float4*)(g_c + rowoff))[hs4] = cn;
        store_h4(rowoff, hs4, hv);
    }
    store_hsum4((size_t)(tp * 256 + bt) * 256, hs4, hsum);
}

// ---------------------------------------------------------------------------
// Root elementwise (node 0, no hsum)
// ---------------------------------------------------------------------------
__global__ __launch_bounds__(256) void level_ew_root(
    const float* __restrict__ b_iou, const float* __restrict__ U_f_b)
{
    const int tid = blockIdx.x * 256 + threadIdx.x;
    const int hs4 = tid & 63;
    const int bt  = tid >> 6;            // 0..255

    const size_t rc0 = ((size_t)bt * NTREEN + 1) * 256;
    const float4 c0 = ((const float4*)(g_c + rc0))[hs4];
    const float4 c1 = ((const float4*)(g_c + rc0 + 256))[hs4];

    const float4* pre = (const float4*)(g_pre + (size_t)bt * NPRE);
    const float4 iI = pre[hs4], iO = pre[64 + hs4], iU = pre[128 + hs4];
    const float4 f0 = pre[192 + hs4], f1 = pre[256 + hs4];

    const float4* bb = (const float4*)b_iou;
    const float4 b0 = bb[hs4], b1 = bb[64 + hs4], b2 = bb[128 + hs4];
    const float4 fb = ((const float4*)U_f_b)[hs4];

    float4 cn; float hv[4];
    #define DOLANE(c_, e_)                                                      \
    {   float csum = sigf(f0.c_ + fb.c_) * c0.c_ + sigf(f1.c_ + fb.c_) * c1.c_; \
        float cv = sigf(iI.c_ + b0.c_) * tanhf_(iU.c_ + b2.c_) + csum;          \
        cn.c_ = cv;                                                             \
        hv[e_] = sigf(iO.c_ + b1.c_) * tanhf_(cv); }
    DOLANE(x, 0) DOLANE(y, 1) DOLANE(z, 2) DOLANE(w, 3)
    #undef DOLANE

    const size_t rowoff = (size_t)bt * NTREEN * 256;
    ((float4*)(g_c + rowoff))[hs4] = cn;
    store_h4(rowoff, hs4, hv);
}

// ---------------------------------------------------------------------------
// Final classifier
// ---------------------------------------------------------------------------
__global__ __launch_bounds__(256) void final_k(
    const float* __restrict__ cls_w, const float* __restrict__ cls_b,
    float* __restrict__ out)
{
    const int b  = blockIdx.x;
    const int hs = threadIdx.x;

    const size_t o1 = (size_t)b           * NTREEN * 256 + hs;
    const size_t o2 = (size_t)(b + BATCH) * NTREEN * 256 + hs;

    float s1 = 0.f, s2 = 0.f;
    #pragma unroll 4
    for (int n = 0; n < NTREEN; n++) {
        s1 += __bfloat162float(g_h_hi[o1 + (size_t)n * 256])
            + __bfloat162float(g_h_lo[o1 + (size_t)n * 256]);
        s2 += __bfloat162float(g_h_hi[o2 + (size_t)n * 256])
            + __bfloat162float(g_h_lo[o2 + (size_t)n * 256]);
    }
    const float d = fabsf(s1 - s2) * (1.0f / (float)NTREEN);

    float v0 = d * cls_w[hs];
    float v1 = d * cls_w[256 + hs];

    #pragma unroll
    for (int off = 16; off > 0; off >>= 1) {
        v0 += __shfl_down_sync(0xffffffffu, v0, off);
        v1 += __shfl_down_sync(0xffffffffu, v1, off);
    }
    __shared__ float sm0[8], sm1[8];
    const int w = threadIdx.x >> 5, lane = threadIdx.x & 31;
    if (lane == 0) { sm0[w] = v0; sm1[w] = v1; }
    __syncthreads();
    if (threadIdx.x == 0) {
        float t0 = 0.f, t1 = 0.f;
        #pragma unroll
        for (int k = 0; k < 8; k++) { t0 += sm0[k]; t1 += sm1[k]; }
        out[b * 2 + 0] = t0 + cls_b[0];
        out[b * 2 + 1] = t1 + cls_b[1];
    }
}

// ---------------------------------------------------------------------------
// Launch
// ---------------------------------------------------------------------------
extern "C" void kernel_launch(void* const* d_in, const int* in_sizes, int n_in,
                              void* d_out, int out_size)
{
    (void)in_sizes; (void)n_in; (void)out_size;
    const int*   types1 = (const int*)  d_in[0];
    const int*   types2 = (const int*)  d_in[1];
    const float* emb    = (const float*)d_in[2];
    const float* W_iou  = (const float*)d_in[3];
    const float* U_iou  = (const float*)d_in[4];
    const float* b_iou  = (const float*)d_in[5];
    const float* U_f_w  = (const float*)d_in[6];
    const float* U_f_b  = (const float*)d_in[7];
    const float* cls_w  = (const float*)d_in[8];
    const float* cls_b  = (const float*)d_in[9];
    float* out = (float*)d_out;

    cudaFuncSetAttribute(gemm_f<0>, cudaFuncAttributeMaxDynamicSharedMemorySize, SMT);
    cudaFuncSetAttribute(gemm_f<1>, cudaFuncAttributeMaxDynamicSharedMemorySize, SMT);

    // 0) prep: split emb + weights into bf16 hi/lo planes
    split_emb<<<VOCABN, 256>>>(emb);
    split_wt<<<768, 256>>>(W_iou);
    build_wc<<<NPRE, 256>>>(U_iou, U_f_w);

    // 1) vocab table: g_table[v] = W_iou @ emb[v]
    gemm_f<0><<<dim3(VOCABN / 128, 6), 256, SMT>>>(0);

    // 2) leaves (+ hsum for level 8)
    leaf_ew_pair<<<16384, 256>>>(types1, types2, b_iou);

    // 3) internal levels 8..1 (GEMM -> fused ew+hsum)
    for (int lvl = 8; lvl >= 1; --lvl) {
        const int base = (1 << lvl) - 1;
        gemm_f<1><<<dim3((BTN << lvl) / 128, 10), 256, SMT>>>(base);
        level_ew_pair<<<64 << (lvl - 1), 256>>>(b_iou, U_f_b, base);
    }

    // 4) root level
    gemm_f<1><<<dim3(2, 10), 256, SMT>>>(0);
    level_ew_root<<<64, 256>>>(b_iou, U_f_b);

    // 5) classifier
    final_k<<<BATCH, 256>>>(cls_w, cls_b, out);
}

// round 10
// speedup vs baseline: 1.4270x; 1.1866x over previous
#include <cuda_runtime.h>
#include <cuda_bf16.h>
#include <stdint.h>
#include <math.h>

// ---------------------------------------------------------------------------
// Problem constants
// ---------------------------------------------------------------------------
#define VOCABN 32000
#define BATCH  128
#define BTN    256          // 2*BATCH
#define NTREEN 1023
#define NPRE   1280         // iou(768) | f0(256) | f1(256)

// ---------------------------------------------------------------------------
// Scratch (device globals)
// h / hsum: plain bf16 (single plane). emb + weights: bf16 hi/lo planes.
// ---------------------------------------------------------------------------
__device__ __align__(16) __nv_bfloat16 g_emb_hi[(size_t)VOCABN * 256];
__device__ __align__(16) __nv_bfloat16 g_emb_lo[(size_t)VOCABN * 256];
__device__ __align__(16) __nv_bfloat16 g_Wt_hi[768 * 256];
__device__ __align__(16) __nv_bfloat16 g_Wt_lo[768 * 256];
__device__ __align__(16) __nv_bfloat16 g_Wc_hi[NPRE * 256];
__device__ __align__(16) __nv_bfloat16 g_Wc_lo[NPRE * 256];
__device__ __align__(16) __nv_bfloat16 g_h   [(size_t)BTN * NTREEN * 256];
__device__ __align__(16) __nv_bfloat16 g_hsum[(size_t)65536 * 256];
__device__ __align__(16) float g_c    [(size_t)BTN * NTREEN * 256];
__device__ __align__(16) float g_pre  [(size_t)65536 * NPRE];
__device__ __align__(16) float g_table[(size_t)VOCABN * 768];

// ---------------------------------------------------------------------------
// Helpers
// ---------------------------------------------------------------------------
__device__ __forceinline__ float sigf(float x)   { return 1.0f / (1.0f + __expf(-x)); }
__device__ __forceinline__ float tanhf_(float x) { return 2.0f / (1.0f + __expf(-2.0f * x)) - 1.0f; }

__device__ __forceinline__ void split16(float x, unsigned short& hb, unsigned short& lb) {
    __nv_bfloat16 h = __float2bfloat16(x);
    float hf = __bfloat162float(h);
    __nv_bfloat16 l = __float2bfloat16(x - hf);
    hb = __bfloat16_as_ushort(h);
    lb = __bfloat16_as_ushort(l);
}

__device__ __forceinline__ uint32_t smem_u32(const void* p) {
    uint32_t a;
    asm("{ .reg .u64 t; cvta.to.shared.u64 t, %1; cvt.u32.u64 %0, t; }" : "=r"(a) : "l"(p));
    return a;
}

// ---------------------------------------------------------------------------
// Baseline-PTX tensor ops + cp.async
// ---------------------------------------------------------------------------
__device__ __forceinline__ void ldm_x4(uint32_t r[4], uint32_t addr) {
    asm volatile("ldmatrix.sync.aligned.m8n8.x4.shared.b16 {%0,%1,%2,%3}, [%4];"
        : "=r"(r[0]), "=r"(r[1]), "=r"(r[2]), "=r"(r[3]) : "r"(addr));
}
__device__ __forceinline__ void ldm_x2(uint32_t r[2], uint32_t addr) {
    asm volatile("ldmatrix.sync.aligned.m8n8.x2.shared.b16 {%0,%1}, [%2];"
        : "=r"(r[0]), "=r"(r[1]) : "r"(addr));
}
__device__ __forceinline__ void mma_bf16(float c[4], const uint32_t a[4], const uint32_t b[2]) {
    asm volatile("mma.sync.aligned.m16n8k16.row.col.f32.bf16.bf16.f32 "
        "{%0,%1,%2,%3}, {%4,%5,%6,%7}, {%8,%9}, {%0,%1,%2,%3};"
        : "+f"(c[0]), "+f"(c[1]), "+f"(c[2]), "+f"(c[3])
        : "r"(a[0]), "r"(a[1]), "r"(a[2]), "r"(a[3]), "r"(b[0]), "r"(b[1]));
}
#define CP16(dst, src) asm volatile("cp.async.cg.shared.global [%0], [%1], 16;" :: "r"(dst), "l"(src))
#define CP_COMMIT()    asm volatile("cp.async.commit_group;" ::: "memory")
#define CP_WAIT0()     asm volatile("cp.async.wait_group 0;" ::: "memory")

// ---------------------------------------------------------------------------
// Prep kernels (device globals referenced from device code only)
// ---------------------------------------------------------------------------
__global__ __launch_bounds__(256) void split_emb(const float* __restrict__ src)
{
    const int idx = blockIdx.x * 256 + threadIdx.x;
    unsigned short h, l;
    split16(src[idx], h, l);
    g_emb_hi[idx] = __ushort_as_bfloat16(h);
    g_emb_lo[idx] = __ushort_as_bfloat16(l);
}

__global__ __launch_bounds__(256) void split_wt(const float* __restrict__ src)
{
    const int idx = blockIdx.x * 256 + threadIdx.x;
    unsigned short h, l;
    split16(src[idx], h, l);
    g_Wt_hi[idx] = __ushort_as_bfloat16(h);
    g_Wt_lo[idx] = __ushort_as_bfloat16(l);
}

// Wc rows: [0:768)=U_iou, [768:1024)=U_f_w, [1024:1280)=U_f_w
__global__ __launch_bounds__(256) void build_wc(
    const float* __restrict__ U_iou, const float* __restrict__ U_f_w)
{
    const int idx = blockIdx.x * 256 + threadIdx.x;
    const int n = idx >> 8, k = idx & 255;
    const float v = (n < 768) ? U_iou[n * 256 + k]
                              : U_f_w[((n - 768) & 255) * 256 + k];
    unsigned short h, l;
    split16(v, h, l);
    g_Wc_hi[idx] = __ushort_as_bfloat16(h);
    g_Wc_lo[idx] = __ushort_as_bfloat16(l);
}

// ---------------------------------------------------------------------------
// Table GEMM (3-pass hi/lo, Round-7 proven config, unchanged).
// g_table[v] = W_iou @ emb[v].  CTA 128x128, K = 4x64, 64KB smem, 2 CTA/SM.
// ---------------------------------------------------------------------------
#define T_SM_AH 0u
#define T_SM_AL 16384u
#define T_SM_BH 32768u
#define T_SM_BL 49152u
#define T_SMT   65536

__global__ __launch_bounds__(256, 2) void gemm_table()
{
    extern __shared__ char smem[];
    const uint32_t sb = smem_u32(smem);
    const int tid = threadIdx.x, wid = tid >> 5, lane = tid & 31;
    const int bm = blockIdx.x * 128;
    const int bn = blockIdx.y * 128;

    const __nv_bfloat16* ahi = g_emb_hi + (size_t)(bm + (tid >> 1)) * 256 + (tid & 1) * 32;
    const __nv_bfloat16* alo = g_emb_lo + (size_t)(bm + (tid >> 1)) * 256 + (tid & 1) * 32;
    const __nv_bfloat16* bhi = g_Wt_hi + (size_t)(bn + (tid >> 1)) * 256 + (tid & 1) * 32;
    const __nv_bfloat16* blo = g_Wt_lo + (size_t)(bn + (tid >> 1)) * 256 + (tid & 1) * 32;

    const uint32_t rowoff = (uint32_t)(tid >> 1) * 128u;
    const uint32_t rxor   = (uint32_t)(((tid >> 1) & 7) << 4);

    const int wm = (wid & 1) * 64;
    const int wn = (wid >> 1) * 32;
    float acc[4][4][4] = {};

    #pragma unroll 1
    for (int kc = 0; kc < 4; kc++) {
        const int k0 = kc * 64;
        #pragma unroll
        for (int j = 0; j < 4; j++) {
            const uint32_t xo = (uint32_t)((tid & 1) * 64 + j * 16) ^ rxor;
            const uint32_t d = rowoff + xo;
            CP16(sb + T_SM_AH + d, ahi + k0 + j * 8);
            CP16(sb + T_SM_AL + d, alo + k0 + j * 8);
            CP16(sb + T_SM_BH + d, bhi + k0 + j * 8);
            CP16(sb + T_SM_BL + d, blo + k0 + j * 8);
        }
        CP_COMMIT();
        CP_WAIT0();
        __syncthreads();

        #pragma unroll
        for (int kg = 0; kg < 4; kg++) {
            uint32_t bh[4][2], bl[4][2];
            #pragma unroll
            for (int nf = 0; nf < 4; nf++) {
                const uint32_t nrow = (uint32_t)(wn + nf * 8 + (lane & 7));
                const uint32_t x = (uint32_t)(kg * 32 + ((lane >> 3) & 1) * 16);
                const uint32_t sw = nrow * 128u + (x ^ ((nrow & 7u) << 4));
                ldm_x2(bh[nf], sb + T_SM_BH + sw);
                ldm_x2(bl[nf], sb + T_SM_BL + sw);
            }
            #pragma unroll
            for (int mf = 0; mf < 4; mf++) {
                const uint32_t mrow = (uint32_t)(wm + mf * 16 + (lane & 15));
                const uint32_t x = (uint32_t)(kg * 32 + (lane >> 4) * 16);
                const uint32_t sw = mrow * 128u + (x ^ ((mrow & 7u) << 4));
                uint32_t a[4];
                ldm_x4(a, sb + T_SM_AH + sw);
                #pragma unroll
                for (int nf = 0; nf < 4; nf++) {
                    mma_bf16(acc[mf][nf], a, bh[nf]);
                    mma_bf16(acc[mf][nf], a, bl[nf]);
                }
                ldm_x4(a, sb + T_SM_AL + sw);
                #pragma unroll
                for (int nf = 0; nf < 4; nf++)
                    mma_bf16(acc[mf][nf], a, bh[nf]);
            }
        }
        __syncthreads();
    }

    #pragma unroll
    for (int mf = 0; mf < 4; mf++) {
        const int row = bm + wm + mf * 16 + (lane >> 2);
        #pragma unroll
        for (int nf = 0; nf < 4; nf++) {
            const int col = bn + wn + nf * 8 + (lane & 3) * 2;
            *(float2*)&g_table[(size_t)row * 768 + col] =
                make_float2(acc[mf][nf][0], acc[mf][nf][1]);
            *(float2*)&g_table[(size_t)(row + 8) * 768 + col] =
                make_float2(acc[mf][nf][2], acc[mf][nf][3]);
        }
    }
}

// ---------------------------------------------------------------------------
// Level GEMM (2-pass): A bf16 single plane (h / hsum), B hi/lo (Wc).
// pre[M,1280] = A[M,256] @ Wc[1280,256]^T.
// CTA 128x128, K = 4x64, smem: A 16K | BH 16K | BL 16K = 48K, 2 CTA/SM.
// tiles 0-5: A = hsum (iou cols) | 6,7: A = child0 (f0) | 8,9: child1 (f1)
// ---------------------------------------------------------------------------
#define L_SM_A  0u
#define L_SM_BH 16384u
#define L_SM_BL 32768u
#define L_SMT   49152

__global__ __launch_bounds__(256, 2) void gemm_level(int base)
{
    extern __shared__ char smem[];
    const uint32_t sb = smem_u32(smem);
    const int tid = threadIdx.x, wid = tid >> 5, lane = tid & 31;
    const int bm = blockIdx.x * 128;
    const int tile = blockIdx.y;
    const int bn = tile * 128;

    // A source (single bf16 plane)
    const __nv_bfloat16* a;
    {
        const int r = bm + (tid >> 1);
        if (tile < 6) {
            a = g_hsum + (size_t)r * 256;
        } else {
            const int s = (tile - 6) >> 1;
            const int j = r >> 8, bt = r & 255, node = base + j;
            a = g_h + ((size_t)bt * NTREEN + 2 * node + 1 + s) * 256;
        }
        a += (tid & 1) * 32;
    }
    const __nv_bfloat16* bhi = g_Wc_hi + (size_t)(bn + (tid >> 1)) * 256 + (tid & 1) * 32;
    const __nv_bfloat16* blo = g_Wc_lo + (size_t)(bn + (tid >> 1)) * 256 + (tid & 1) * 32;

    const uint32_t rowoff = (uint32_t)(tid >> 1) * 128u;
    const uint32_t rxor   = (uint32_t)(((tid >> 1) & 7) << 4);

    const int wm = (wid & 1) * 64;
    const int wn = (wid >> 1) * 32;
    float acc[4][4][4] = {};

    #pragma unroll 1
    for (int kc = 0; kc < 4; kc++) {
        const int k0 = kc * 64;
        #pragma unroll
        for (int j = 0; j < 4; j++) {
            const uint32_t xo = (uint32_t)((tid & 1) * 64 + j * 16) ^ rxor;
            const uint32_t d = rowoff + xo;
            CP16(sb + L_SM_A  + d, a   + k0 + j * 8);
            CP16(sb + L_SM_BH + d, bhi + k0 + j * 8);
            CP16(sb + L_SM_BL + d, blo + k0 + j * 8);
        }
        CP_COMMIT();
        CP_WAIT0();
        __syncthreads();

        #pragma unroll
        for (int kg = 0; kg < 4; kg++) {
            uint32_t bh[4][2], bl[4][2];
            #pragma unroll
            for (int nf = 0; nf < 4; nf++) {
                const uint32_t nrow = (uint32_t)(wn + nf * 8 + (lane & 7));
                const uint32_t x = (uint32_t)(kg * 32 + ((lane >> 3) & 1) * 16);
                const uint32_t sw = nrow * 128u + (x ^ ((nrow & 7u) << 4));
                ldm_x2(bh[nf], sb + L_SM_BH + sw);
                ldm_x2(bl[nf], sb + L_SM_BL + sw);
            }
            #pragma unroll
            for (int mf = 0; mf < 4; mf++) {
                const uint32_t mrow = (uint32_t)(wm + mf * 16 + (lane & 15));
                const uint32_t x = (uint32_t)(kg * 32 + (lane >> 4) * 16);
                const uint32_t sw = mrow * 128u + (x ^ ((mrow & 7u) << 4));
                uint32_t a4[4];
                ldm_x4(a4, sb + L_SM_A + sw);
                #pragma unroll
                for (int nf = 0; nf < 4; nf++) {
                    mma_bf16(acc[mf][nf], a4, bh[nf]);   // a * B_hi
                    mma_bf16(acc[mf][nf], a4, bl[nf]);   // a * B_lo
                }
            }
        }
        __syncthreads();
    }

    #pragma unroll
    for (int mf = 0; mf < 4; mf++) {
        const int row = bm + wm + mf * 16 + (lane >> 2);
        #pragma unroll
        for (int nf = 0; nf < 4; nf++) {
            const int col = bn + wn + nf * 8 + (lane & 3) * 2;
            *(float2*)&g_pre[(size_t)row * NPRE + col] =
                make_float2(acc[mf][nf][0], acc[mf][nf][1]);
            *(float2*)&g_pre[(size_t)(row + 8) * NPRE + col] =
                make_float2(acc[mf][nf][2], acc[mf][nf][3]);
        }
    }
}

// ---------------------------------------------------------------------------
// h / hsum store helpers: fp32 -> plain bf16 plane
// ---------------------------------------------------------------------------
__device__ __forceinline__ void store_h4(size_t rowoff, int hs4, const float h[4]) {
    unsigned short b[4];
    #pragma unroll
    for (int e = 0; e < 4; e++) b[e] = __bfloat16_as_ushort(__float2bfloat16(h[e]));
    ((uint2*)(g_h + rowoff))[hs4] =
        make_uint2(b[0] | ((unsigned)b[1] << 16), b[2] | ((unsigned)b[3] << 16));
}
__device__ __forceinline__ void store_hsum4(size_t rowoff, int hs4, const float h[4]) {
    unsigned short b[4];
    #pragma unroll
    for (int e = 0; e < 4; e++) b[e] = __bfloat16_as_ushort(__float2bfloat16(h[e]));
    ((uint2*)(g_hsum + rowoff))[hs4] =
        make_uint2(b[0] | ((unsigned)b[1] << 16), b[2] | ((unsigned)b[3] << 16));
}

// ---------------------------------------------------------------------------
// Leaf elementwise, fused sibling pair + hsum.
// ---------------------------------------------------------------------------
__global__ __launch_bounds__(256) void leaf_ew_pair(
    const int* __restrict__ types1, const int* __restrict__ types2,
    const float* __restrict__ b_iou)
{
    const int tid = blockIdx.x * 256 + threadIdx.x;
    const int hs4 = tid & 63;
    const int q   = tid >> 6;            // 0 .. 256*256-1
    const int bt  = q & 255;
    const int tp  = q >> 8;              // pair 0..255

    const int* ty = (bt < BATCH) ? types1 + bt * NTREEN
                                 : types2 + (bt - BATCH) * NTREEN;
    const float4* bb = (const float4*)b_iou;
    const float4 b0 = bb[hs4], b1 = bb[64 + hs4], b2 = bb[128 + hs4];

    float hsum[4] = {0.f, 0.f, 0.f, 0.f};
    #pragma unroll
    for (int s = 0; s < 2; s++) {
        const int node = 511 + 2 * tp + s;
        const int v = ty[node];
        const float4* t = (const float4*)(g_table + (size_t)v * 768);
        const float4 i4 = t[hs4], o4 = t[64 + hs4], u4 = t[128 + hs4];

        float4 cn; float hv[4];
        #define DOLANE(c_, e_)                                       \
        {   float cv = sigf(i4.c_ + b0.c_) * tanhf_(u4.c_ + b2.c_);  \
            cn.c_ = cv;                                              \
            hv[e_] = sigf(o4.c_ + b1.c_) * tanhf_(cv);               \
            hsum[e_] += hv[e_]; }
        DOLANE(x, 0) DOLANE(y, 1) DOLANE(z, 2) DOLANE(w, 3)
        #undef DOLANE

        const size_t rowoff = ((size_t)bt * NTREEN + node) * 256;
        ((float4*)(g_c + rowoff))[hs4] = cn;
        store_h4(rowoff, hs4, hv);
    }
    store_hsum4((size_t)(tp * 256 + bt) * 256, hs4, hsum);
}

// ---------------------------------------------------------------------------
// Internal-level elementwise, fused sibling pair + hsum.
// ---------------------------------------------------------------------------
__global__ __launch_bounds__(256) void level_ew_pair(
    const float* __restrict__ b_iou, const float* __restrict__ U_f_b, int cbase)
{
    const int tid = blockIdx.x * 256 + threadIdx.x;
    const int hs4 = tid & 63;
    const int q   = tid >> 6;
    const int bt  = q & 255;
    const int tp  = q >> 8;

    const float4* bb = (const float4*)b_iou;
    const float4 b0 = bb[hs4], b1 = bb[64 + hs4], b2 = bb[128 + hs4];
    const float4 fb = ((const float4*)U_f_b)[hs4];

    float hsum[4] = {0.f, 0.f, 0.f, 0.f};
    #pragma unroll
    for (int s = 0; s < 2; s++) {
        const int node = cbase + 2 * tp + s;
        const int i    = (2 * tp + s) * 256 + bt;

        const size_t rc0 = ((size_t)bt * NTREEN + 2 * node + 1) * 256;
        const float4 c0 = ((const float4*)(g_c + rc0))[hs4];
        const float4 c1 = ((const float4*)(g_c + rc0 + 256))[hs4];

        const float4* pre = (const float4*)(g_pre + (size_t)i * NPRE);
        const float4 iI = pre[hs4], iO = pre[64 + hs4], iU = pre[128 + hs4];
        const float4 f0 = pre[192 + hs4], f1 = pre[256 + hs4];

        float4 cn; float hv[4];
        #define DOLANE(c_, e_)                                                      \
        {   float csum = sigf(f0.c_ + fb.c_) * c0.c_ + sigf(f1.c_ + fb.c_) * c1.c_; \
            float cv = sigf(iI.c_ + b0.c_) * tanhf_(iU.c_ + b2.c_) + csum;          \
            cn.c_ = cv;                                                             \
            hv[e_] = sigf(iO.c_ + b1.c_) * tanhf_(cv);                              \
            hsum[e_] += hv[e_]; }
        DOLANE(x, 0) DOLANE(y, 1) DOLANE(z, 2) DOLANE(w, 3)
        #undef DOLANE

        const size_t rowoff = ((size_t)bt * NTREEN + node) * 256;
        ((float4*)(g_c + rowoff))[hs4] = cn;
        store_h4(rowoff, hs4, hv);
    }
    store_hsum4((size_t)(tp * 256 + bt) * 256, hs4, hsum);
}

// ---------------------------------------------------------------------------
// Root elementwise (node 0, no hsum)
// ---------------------------------------------------------------------------
__global__ __launch_bounds__(256) void level_ew_root(
    const float* __restrict__ b_iou, const float* __restrict__ U_f_b)
{
    const int tid = blockIdx.x * 256 + threadIdx.x;
    const int hs4 = tid & 63;
    const int bt  = tid >> 6;            // 0..255

    const size_t rc0 = ((size_t)bt * NTREEN + 1) * 256;
    const float4 c0 = ((const float4*)(g_c + rc0))[hs4];
    const float4 c1 = ((const float4*)(g_c + rc0 + 256))[hs4];

    const float4* pre = (const float4*)(g_pre + (size_t)bt * NPRE);
    const float4 iI = pre[hs4], iO = pre[64 + hs4], iU = pre[128 + hs4];
    const float4 f0 = pre[192 + hs4], f1 = pre[256 + hs4];

    const float4* bb = (const float4*)b_iou;
    const float4 b0 = bb[hs4], b1 = bb[64 + hs4], b2 = bb[128 + hs4];
    const float4 fb = ((const float4*)U_f_b)[hs4];

    float4 cn; float hv[4];
    #define DOLANE(c_, e_)                                                      \
    {   float csum = sigf(f0.c_ + fb.c_) * c0.c_ + sigf(f1.c_ + fb.c_) * c1.c_; \
        float cv = sigf(iI.c_ + b0.c_) * tanhf_(iU.c_ + b2.c_) + csum;          \
        cn.c_ = cv;                                                             \
        hv[e_] = sigf(iO.c_ + b1.c_) * tanhf_(cv); }
    DOLANE(x, 0) DOLANE(y, 1) DOLANE(z, 2) DOLANE(w, 3)
    #undef DOLANE

    const size_t rowoff = (size_t)bt * NTREEN * 256;
    ((float4*)(g_c + rowoff))[hs4] = cn;
    store_h4(rowoff, hs4, hv);
}

// ---------------------------------------------------------------------------
// Final classifier (reads bf16 h plane)
// ---------------------------------------------------------------------------
__global__ __launch_bounds__(256) void final_k(
    const float* __restrict__ cls_w, const float* __restrict__ cls_b,
    float* __restrict__ out)
{
    const int b  = blockIdx.x;
    const int hs = threadIdx.x;

    const size_t o1 = (size_t)b           * NTREEN * 256 + hs;
    const size_t o2 = (size_t)(b + BATCH) * NTREEN * 256 + hs;

    float s1 = 0.f, s2 = 0.f;
    #pragma unroll 4
    for (int n = 0; n < NTREEN; n++) {
        s1 += __bfloat162float(g_h[o1 + (size_t)n * 256]);
        s2 += __bfloat162float(g_h[o2 + (size_t)n * 256]);
    }
    const float d = fabsf(s1 - s2) * (1.0f / (float)NTREEN);

    float v0 = d * cls_w[hs];
    float v1 = d * cls_w[256 + hs];

    #pragma unroll
    for (int off = 16; off > 0; off >>= 1) {
        v0 += __shfl_down_sync(0xffffffffu, v0, off);
        v1 += __shfl_down_sync(0xffffffffu, v1, off);
    }
    __shared__ float sm0[8], sm1[8];
    const int w = threadIdx.x >> 5, lane = threadIdx.x & 31;
    if (lane == 0) { sm0[w] = v0; sm1[w] = v1; }
    __syncthreads();
    if (threadIdx.x == 0) {
        float t0 = 0.f, t1 = 0.f;
        #pragma unroll
        for (int k = 0; k < 8; k++) { t0 += sm0[k]; t1 += sm1[k]; }
        out[b * 2 + 0] = t0 + cls_b[0];
        out[b * 2 + 1] = t1 + cls_b[1];
    }
}

// ---------------------------------------------------------------------------
// Launch
// ---------------------------------------------------------------------------
extern "C" void kernel_launch(void* const* d_in, const int* in_sizes, int n_in,
                              void* d_out, int out_size)
{
    (void)in_sizes; (void)n_in; (void)out_size;
    const int*   types1 = (const int*)  d_in[0];
    const int*   types2 = (const int*)  d_in[1];
    const float* emb    = (const float*)d_in[2];
    const float* W_iou  = (const float*)d_in[3];
    const float* U_iou  = (const float*)d_in[4];
    const float* b_iou  = (const float*)d_in[5];
    const float* U_f_w  = (const float*)d_in[6];
    const float* U_f_b  = (const float*)d_in[7];
    const float* cls_w  = (const float*)d_in[8];
    const float* cls_b  = (const float*)d_in[9];
    float* out = (float*)d_out;

    cudaFuncSetAttribute(gemm_table, cudaFuncAttributeMaxDynamicSharedMemorySize, T_SMT);
    cudaFuncSetAttribute(gemm_level, cudaFuncAttributeMaxDynamicSharedMemorySize, L_SMT);

    // 0) prep: split emb + weights into bf16 hi/lo planes
    split_emb<<<VOCABN, 256>>>(emb);
    split_wt<<<768, 256>>>(W_iou);
    build_wc<<<NPRE, 256>>>(U_iou, U_f_w);

    // 1) vocab table: g_table[v] = W_iou @ emb[v]
    gemm_table<<<dim3(VOCABN / 128, 6), 256, T_SMT>>>();

    // 2) leaves (+ hsum for level 8)
    leaf_ew_pair<<<16384, 256>>>(types1, types2, b_iou);

    // 3) internal levels 8..1 (2-pass GEMM -> fused ew+hsum)
    for (int lvl = 8; lvl >= 1; --lvl) {
        const int base = (1 << lvl) - 1;
        gemm_level<<<dim3((BTN << lvl) / 128, 10), 256, L_SMT>>>(base);
        level_ew_pair<<<64 << (lvl - 1), 256>>>(b_iou, U_f_b, base);
    }

    // 4) root level
    gemm_level<<<dim3(2, 10), 256, L_SMT>>>(0);
    level_ew_root<<<64, 256>>>(b_iou, U_f_b);

    // 5) classifier
    final_k<<<BATCH, 256>>>(cls_w, cls_b, out);
}

// round 11
// speedup vs baseline: 1.6942x; 1.1873x over previous
#include <cuda_runtime.h>
#include <cuda_bf16.h>
#include <cuda_fp16.h>
#include <stdint.h>
#include <math.h>

// ---------------------------------------------------------------------------
// Problem constants
// ---------------------------------------------------------------------------
#define VOCABN 32000
#define BATCH  128
#define BTN    256          // 2*BATCH
#define NTREEN 1023
#define NPRE   1280         // iou(768) | f0(256) | f1(256)

// ---------------------------------------------------------------------------
// Scratch (device globals)
// h / hsum: fp16 (11-bit mantissa, |h|<1, |hsum|<2).
// Wc: single fp16 plane. emb/Wt (table path): bf16 hi/lo planes (exact-ish).
// ---------------------------------------------------------------------------
__device__ __align__(16) __nv_bfloat16 g_emb_hi[(size_t)VOCABN * 256];
__device__ __align__(16) __nv_bfloat16 g_emb_lo[(size_t)VOCABN * 256];
__device__ __align__(16) __nv_bfloat16 g_Wt_hi[768 * 256];
__device__ __align__(16) __nv_bfloat16 g_Wt_lo[768 * 256];
__device__ __align__(16) __half        g_Wc   [NPRE * 256];
__device__ __align__(16) __half        g_h    [(size_t)BTN * NTREEN * 256];
__device__ __align__(16) __half        g_hsum [(size_t)65536 * 256];
__device__ __align__(16) float g_c    [(size_t)BTN * NTREEN * 256];
__device__ __align__(16) float g_pre  [(size_t)65536 * NPRE];
__device__ __align__(16) float g_table[(size_t)VOCABN * 768];

// ---------------------------------------------------------------------------
// Helpers
// ---------------------------------------------------------------------------
__device__ __forceinline__ float sigf(float x)   { return 1.0f / (1.0f + __expf(-x)); }
__device__ __forceinline__ float tanhf_(float x) { return 2.0f / (1.0f + __expf(-2.0f * x)) - 1.0f; }

__device__ __forceinline__ void split16(float x, unsigned short& hb, unsigned short& lb) {
    __nv_bfloat16 h = __float2bfloat16(x);
    float hf = __bfloat162float(h);
    __nv_bfloat16 l = __float2bfloat16(x - hf);
    hb = __bfloat16_as_ushort(h);
    lb = __bfloat16_as_ushort(l);
}

__device__ __forceinline__ uint32_t smem_u32(const void* p) {
    uint32_t a;
    asm("{ .reg .u64 t; cvta.to.shared.u64 t, %1; cvt.u32.u64 %0, t; }" : "=r"(a) : "l"(p));
    return a;
}

// ---------------------------------------------------------------------------
// Baseline-PTX tensor ops + cp.async
// ---------------------------------------------------------------------------
__device__ __forceinline__ void ldm_x4(uint32_t r[4], uint32_t addr) {
    asm volatile("ldmatrix.sync.aligned.m8n8.x4.shared.b16 {%0,%1,%2,%3}, [%4];"
        : "=r"(r[0]), "=r"(r[1]), "=r"(r[2]), "=r"(r[3]) : "r"(addr));
}
__device__ __forceinline__ void ldm_x2(uint32_t r[2], uint32_t addr) {
    asm volatile("ldmatrix.sync.aligned.m8n8.x2.shared.b16 {%0,%1}, [%2];"
        : "=r"(r[0]), "=r"(r[1]) : "r"(addr));
}
__device__ __forceinline__ void mma_bf16(float c[4], const uint32_t a[4], const uint32_t b[2]) {
    asm volatile("mma.sync.aligned.m16n8k16.row.col.f32.bf16.bf16.f32 "
        "{%0,%1,%2,%3}, {%4,%5,%6,%7}, {%8,%9}, {%0,%1,%2,%3};"
        : "+f"(c[0]), "+f"(c[1]), "+f"(c[2]), "+f"(c[3])
        : "r"(a[0]), "r"(a[1]), "r"(a[2]), "r"(a[3]), "r"(b[0]), "r"(b[1]));
}
__device__ __forceinline__ void mma_f16(float c[4], const uint32_t a[4], const uint32_t b[2]) {
    asm volatile("mma.sync.aligned.m16n8k16.row.col.f32.f16.f16.f32 "
        "{%0,%1,%2,%3}, {%4,%5,%6,%7}, {%8,%9}, {%0,%1,%2,%3};"
        : "+f"(c[0]), "+f"(c[1]), "+f"(c[2]), "+f"(c[3])
        : "r"(a[0]), "r"(a[1]), "r"(a[2]), "r"(a[3]), "r"(b[0]), "r"(b[1]));
}
#define CP16(dst, src) asm volatile("cp.async.cg.shared.global [%0], [%1], 16;" :: "r"(dst), "l"(src))
#define CP_COMMIT()    asm volatile("cp.async.commit_group;" ::: "memory")
#define CP_WAIT0()     asm volatile("cp.async.wait_group 0;" ::: "memory")

// ---------------------------------------------------------------------------
// Prep kernels (device globals referenced from device code only)
// ---------------------------------------------------------------------------
__global__ __launch_bounds__(256) void split_emb(const float* __restrict__ src)
{
    const int idx = blockIdx.x * 256 + threadIdx.x;
    unsigned short h, l;
    split16(src[idx], h, l);
    g_emb_hi[idx] = __ushort_as_bfloat16(h);
    g_emb_lo[idx] = __ushort_as_bfloat16(l);
}

__global__ __launch_bounds__(256) void split_wt(const float* __restrict__ src)
{
    const int idx = blockIdx.x * 256 + threadIdx.x;
    unsigned short h, l;
    split16(src[idx], h, l);
    g_Wt_hi[idx] = __ushort_as_bfloat16(h);
    g_Wt_lo[idx] = __ushort_as_bfloat16(l);
}

// Wc rows: [0:768)=U_iou, [768:1024)=U_f_w, [1024:1280)=U_f_w  (fp16 single)
__global__ __launch_bounds__(256) void build_wc(
    const float* __restrict__ U_iou, const float* __restrict__ U_f_w)
{
    const int idx = blockIdx.x * 256 + threadIdx.x;
    const int n = idx >> 8, k = idx & 255;
    const float v = (n < 768) ? U_iou[n * 256 + k]
                              : U_f_w[((n - 768) & 255) * 256 + k];
    g_Wc[idx] = __float2half_rn(v);
}

// ---------------------------------------------------------------------------
// Table GEMM (3-pass bf16 hi/lo, proven config, unchanged).
// g_table[v] = W_iou @ emb[v].  CTA 128x128, K = 4x64, 64KB smem, 2 CTA/SM.
// ---------------------------------------------------------------------------
#define T_SM_AH 0u
#define T_SM_AL 16384u
#define T_SM_BH 32768u
#define T_SM_BL 49152u
#define T_SMT   65536

__global__ __launch_bounds__(256, 2) void gemm_table()
{
    extern __shared__ char smem[];
    const uint32_t sb = smem_u32(smem);
    const int tid = threadIdx.x, wid = tid >> 5, lane = tid & 31;
    const int bm = blockIdx.x * 128;
    const int bn = blockIdx.y * 128;

    const __nv_bfloat16* ahi = g_emb_hi + (size_t)(bm + (tid >> 1)) * 256 + (tid & 1) * 32;
    const __nv_bfloat16* alo = g_emb_lo + (size_t)(bm + (tid >> 1)) * 256 + (tid & 1) * 32;
    const __nv_bfloat16* bhi = g_Wt_hi + (size_t)(bn + (tid >> 1)) * 256 + (tid & 1) * 32;
    const __nv_bfloat16* blo = g_Wt_lo + (size_t)(bn + (tid >> 1)) * 256 + (tid & 1) * 32;

    const uint32_t rowoff = (uint32_t)(tid >> 1) * 128u;
    const uint32_t rxor   = (uint32_t)(((tid >> 1) & 7) << 4);

    const int wm = (wid & 1) * 64;
    const int wn = (wid >> 1) * 32;
    float acc[4][4][4] = {};

    #pragma unroll 1
    for (int kc = 0; kc < 4; kc++) {
        const int k0 = kc * 64;
        #pragma unroll
        for (int j = 0; j < 4; j++) {
            const uint32_t xo = (uint32_t)((tid & 1) * 64 + j * 16) ^ rxor;
            const uint32_t d = rowoff + xo;
            CP16(sb + T_SM_AH + d, ahi + k0 + j * 8);
            CP16(sb + T_SM_AL + d, alo + k0 + j * 8);
            CP16(sb + T_SM_BH + d, bhi + k0 + j * 8);
            CP16(sb + T_SM_BL + d, blo + k0 + j * 8);
        }
        CP_COMMIT();
        CP_WAIT0();
        __syncthreads();

        #pragma unroll
        for (int kg = 0; kg < 4; kg++) {
            uint32_t bh[4][2], bl[4][2];
            #pragma unroll
            for (int nf = 0; nf < 4; nf++) {
                const uint32_t nrow = (uint32_t)(wn + nf * 8 + (lane & 7));
                const uint32_t x = (uint32_t)(kg * 32 + ((lane >> 3) & 1) * 16);
                const uint32_t sw = nrow * 128u + (x ^ ((nrow & 7u) << 4));
                ldm_x2(bh[nf], sb + T_SM_BH + sw);
                ldm_x2(bl[nf], sb + T_SM_BL + sw);
            }
            #pragma unroll
            for (int mf = 0; mf < 4; mf++) {
                const uint32_t mrow = (uint32_t)(wm + mf * 16 + (lane & 15));
                const uint32_t x = (uint32_t)(kg * 32 + (lane >> 4) * 16);
                const uint32_t sw = mrow * 128u + (x ^ ((mrow & 7u) << 4));
                uint32_t a[4];
                ldm_x4(a, sb + T_SM_AH + sw);
                #pragma unroll
                for (int nf = 0; nf < 4; nf++) {
                    mma_bf16(acc[mf][nf], a, bh[nf]);
                    mma_bf16(acc[mf][nf], a, bl[nf]);
                }
                ldm_x4(a, sb + T_SM_AL + sw);
                #pragma unroll
                for (int nf = 0; nf < 4; nf++)
                    mma_bf16(acc[mf][nf], a, bh[nf]);
            }
        }
        __syncthreads();
    }

    #pragma unroll
    for (int mf = 0; mf < 4; mf++) {
        const int row = bm + wm + mf * 16 + (lane >> 2);
        #pragma unroll
        for (int nf = 0; nf < 4; nf++) {
            const int col = bn + wn + nf * 8 + (lane & 3) * 2;
            *(float2*)&g_table[(size_t)row * 768 + col] =
                make_float2(acc[mf][nf][0], acc[mf][nf][1]);
            *(float2*)&g_table[(size_t)(row + 8) * 768 + col] =
                make_float2(acc[mf][nf][2], acc[mf][nf][3]);
        }
    }
}

// ---------------------------------------------------------------------------
// Level GEMM (single-pass fp16): A = h/hsum fp16, B = Wc fp16.
// pre[M,1280] = A[M,256] @ Wc[1280,256]^T.
// CTA 128x128, K = 4x64, smem: A 16K | B 16K = 32K, 2 CTA/SM.
// tiles 0-5: A = hsum (iou cols) | 6,7: A = child0 (f0) | 8,9: child1 (f1)
// ---------------------------------------------------------------------------
#define L_SM_A 0u
#define L_SM_B 16384u
#define L_SMT  32768

__global__ __launch_bounds__(256, 2) void gemm_level(int base)
{
    extern __shared__ char smem[];
    const uint32_t sb = smem_u32(smem);
    const int tid = threadIdx.x, wid = tid >> 5, lane = tid & 31;
    const int bm = blockIdx.x * 128;
    const int tile = blockIdx.y;
    const int bn = tile * 128;

    // A source (fp16 plane)
    const __half* a;
    {
        const int r = bm + (tid >> 1);
        if (tile < 6) {
            a = g_hsum + (size_t)r * 256;
        } else {
            const int s = (tile - 6) >> 1;
            const int j = r >> 8, bt = r & 255, node = base + j;
            a = g_h + ((size_t)bt * NTREEN + 2 * node + 1 + s) * 256;
        }
        a += (tid & 1) * 32;
    }
    const __half* b = g_Wc + (size_t)(bn + (tid >> 1)) * 256 + (tid & 1) * 32;

    const uint32_t rowoff = (uint32_t)(tid >> 1) * 128u;
    const uint32_t rxor   = (uint32_t)(((tid >> 1) & 7) << 4);

    const int wm = (wid & 1) * 64;
    const int wn = (wid >> 1) * 32;
    float acc[4][4][4] = {};

    #pragma unroll 1
    for (int kc = 0; kc < 4; kc++) {
        const int k0 = kc * 64;
        #pragma unroll
        for (int j = 0; j < 4; j++) {
            const uint32_t xo = (uint32_t)((tid & 1) * 64 + j * 16) ^ rxor;
            const uint32_t d = rowoff + xo;
            CP16(sb + L_SM_A + d, a + k0 + j * 8);
            CP16(sb + L_SM_B + d, b + k0 + j * 8);
        }
        CP_COMMIT();
        CP_WAIT0();
        __syncthreads();

        #pragma unroll
        for (int kg = 0; kg < 4; kg++) {
            uint32_t bf[4][2];
            #pragma unroll
            for (int nf = 0; nf < 4; nf++) {
                const uint32_t nrow = (uint32_t)(wn + nf * 8 + (lane & 7));
                const uint32_t x = (uint32_t)(kg * 32 + ((lane >> 3) & 1) * 16);
                const uint32_t sw = nrow * 128u + (x ^ ((nrow & 7u) << 4));
                ldm_x2(bf[nf], sb + L_SM_B + sw);
            }
            #pragma unroll
            for (int mf = 0; mf < 4; mf++) {
                const uint32_t mrow = (uint32_t)(wm + mf * 16 + (lane & 15));
                const uint32_t x = (uint32_t)(kg * 32 + (lane >> 4) * 16);
                const uint32_t sw = mrow * 128u + (x ^ ((mrow & 7u) << 4));
                uint32_t a4[4];
                ldm_x4(a4, sb + L_SM_A + sw);
                #pragma unroll
                for (int nf = 0; nf < 4; nf++)
                    mma_f16(acc[mf][nf], a4, bf[nf]);
            }
        }
        __syncthreads();
    }

    #pragma unroll
    for (int mf = 0; mf < 4; mf++) {
        const int row = bm + wm + mf * 16 + (lane >> 2);
        #pragma unroll
        for (int nf = 0; nf < 4; nf++) {
            const int col = bn + wn + nf * 8 + (lane & 3) * 2;
            *(float2*)&g_pre[(size_t)row * NPRE + col] =
                make_float2(acc[mf][nf][0], acc[mf][nf][1]);
            *(float2*)&g_pre[(size_t)(row + 8) * NPRE + col] =
                make_float2(acc[mf][nf][2], acc[mf][nf][3]);
        }
    }
}

// ---------------------------------------------------------------------------
// h / hsum store helpers: fp32 -> fp16
// ---------------------------------------------------------------------------
__device__ __forceinline__ void store_h4(size_t rowoff, int hs4, const float h[4]) {
    unsigned short b[4];
    #pragma unroll
    for (int e = 0; e < 4; e++) b[e] = __half_as_ushort(__float2half_rn(h[e]));
    ((uint2*)(g_h + rowoff))[hs4] =
        make_uint2(b[0] | ((unsigned)b[1] << 16), b[2] | ((unsigned)b[3] << 16));
}
__device__ __forceinline__ void store_hsum4(size_t rowoff, int hs4, const float h[4]) {
    unsigned short b[4];
    #pragma unroll
    for (int e = 0; e < 4; e++) b[e] = __half_as_ushort(__float2half_rn(h[e]));
    ((uint2*)(g_hsum + rowoff))[hs4] =
        make_uint2(b[0] | ((unsigned)b[1] << 16), b[2] | ((unsigned)b[3] << 16));
}

// ---------------------------------------------------------------------------
// Leaf elementwise, fused sibling pair + hsum.
// ---------------------------------------------------------------------------
__global__ __launch_bounds__(256) void leaf_ew_pair(
    const int* __restrict__ types1, const int* __restrict__ types2,
    const float* __restrict__ b_iou)
{
    const int tid = blockIdx.x * 256 + threadIdx.x;
    const int hs4 = tid & 63;
    const int q   = tid >> 6;            // 0 .. 256*256-1
    const int bt  = q & 255;
    const int tp  = q >> 8;              // pair 0..255

    const int* ty = (bt < BATCH) ? types1 + bt * NTREEN
                                 : types2 + (bt - BATCH) * NTREEN;
    const float4* bb = (const float4*)b_iou;
    const float4 b0 = bb[hs4], b1 = bb[64 + hs4], b2 = bb[128 + hs4];

    float hsum[4] = {0.f, 0.f, 0.f, 0.f};
    #pragma unroll
    for (int s = 0; s < 2; s++) {
        const int node = 511 + 2 * tp + s;
        const int v = ty[node];
        const float4* t = (const float4*)(g_table + (size_t)v * 768);
        const float4 i4 = t[hs4], o4 = t[64 + hs4], u4 = t[128 + hs4];

        float4 cn; float hv[4];
        #define DOLANE(c_, e_)                                       \
        {   float cv = sigf(i4.c_ + b0.c_) * tanhf_(u4.c_ + b2.c_);  \
            cn.c_ = cv;                                              \
            hv[e_] = sigf(o4.c_ + b1.c_) * tanhf_(cv);               \
            hsum[e_] += hv[e_]; }
        DOLANE(x, 0) DOLANE(y, 1) DOLANE(z, 2) DOLANE(w, 3)
        #undef DOLANE

        const size_t rowoff = ((size_t)bt * NTREEN + node) * 256;
        ((float4*)(g_c + rowoff))[hs4] = cn;
        store_h4(rowoff, hs4, hv);
    }
    store_hsum4((size_t)(tp * 256 + bt) * 256, hs4, hsum);
}

// ---------------------------------------------------------------------------
// Internal-level elementwise, fused sibling pair + hsum.
// ---------------------------------------------------------------------------
__global__ __launch_bounds__(256) void level_ew_pair(
    const float* __restrict__ b_iou, const float* __restrict__ U_f_b, int cbase)
{
    const int tid = blockIdx.x * 256 + threadIdx.x;
    const int hs4 = tid & 63;
    const int q   = tid >> 6;
    const int bt  = q & 255;
    const int tp  = q >> 8;

    const float4* bb = (const float4*)b_iou;
    const float4 b0 = bb[hs4], b1 = bb[64 + hs4], b2 = bb[128 + hs4];
    const float4 fb = ((const float4*)U_f_b)[hs4];

    float hsum[4] = {0.f, 0.f, 0.f, 0.f};
    #pragma unroll
    for (int s = 0; s < 2; s++) {
        const int node = cbase + 2 * tp + s;
        const int i    = (2 * tp + s) * 256 + bt;

        const size_t rc0 = ((size_t)bt * NTREEN + 2 * node + 1) * 256;
        const float4 c0 = ((const float4*)(g_c + rc0))[hs4];
        const float4 c1 = ((const float4*)(g_c + rc0 + 256))[hs4];

        const float4* pre = (const float4*)(g_pre + (size_t)i * NPRE);
        const float4 iI = pre[hs4], iO = pre[64 + hs4], iU = pre[128 + hs4];
        const float4 f0 = pre[192 + hs4], f1 = pre[256 + hs4];

        float4 cn; float hv[4];
        #define DOLANE(c_, e_)                                                      \
        {   float csum = sigf(f0.c_ + fb.c_) * c0.c_ + sigf(f1.c_ + fb.c_) * c1.c_; \
            float cv = sigf(iI.c_ + b0.c_) * tanhf_(iU.c_ + b2.c_) + csum;          \
            cn.c_ = cv;                                                             \
            hv[e_] = sigf(iO.c_ + b1.c_) * tanhf_(cv);                              \
            hsum[e_] += hv[e_]; }
        DOLANE(x, 0) DOLANE(y, 1) DOLANE(z, 2) DOLANE(w, 3)
        #undef DOLANE

        const size_t rowoff = ((size_t)bt * NTREEN + node) * 256;
        ((float4*)(g_c + rowoff))[hs4] = cn;
        store_h4(rowoff, hs4, hv);
    }
    store_hsum4((size_t)(tp * 256 + bt) * 256, hs4, hsum);
}

// ---------------------------------------------------------------------------
// Root elementwise (node 0, no hsum)
// ---------------------------------------------------------------------------
__global__ __launch_bounds__(256) void level_ew_root(
    const float* __restrict__ b_iou, const float* __restrict__ U_f_b)
{
    const int tid = blockIdx.x * 256 + threadIdx.x;
    const int hs4 = tid & 63;
    const int bt  = tid >> 6;            // 0..255

    const size_t rc0 = ((size_t)bt * NTREEN + 1) * 256;
    const float4 c0 = ((const float4*)(g_c + rc0))[hs4];
    const float4 c1 = ((const float4*)(g_c + rc0 + 256))[hs4];

    const float4* pre = (const float4*)(g_pre + (size_t)bt * NPRE);
    const float4 iI = pre[hs4], iO = pre[64 + hs4], iU = pre[128 + hs4];
    const float4 f0 = pre[192 + hs4], f1 = pre[256 + hs4];

    const float4* bb = (const float4*)b_iou;
    const float4 b0 = bb[hs4], b1 = bb[64 + hs4], b2 = bb[128 + hs4];
    const float4 fb = ((const float4*)U_f_b)[hs4];

    float4 cn; float hv[4];
    #define DOLANE(c_, e_)                                                      \
    {   float csum = sigf(f0.c_ + fb.c_) * c0.c_ + sigf(f1.c_ + fb.c_) * c1.c_; \
        float cv = sigf(iI.c_ + b0.c_) * tanhf_(iU.c_ + b2.c_) + csum;          \
        cn.c_ = cv;                                                             \
        hv[e_] = sigf(iO.c_ + b1.c_) * tanhf_(cv); }
    DOLANE(x, 0) DOLANE(y, 1) DOLANE(z, 2) DOLANE(w, 3)
    #undef DOLANE

    const size_t rowoff = (size_t)bt * NTREEN * 256;
    ((float4*)(g_c + rowoff))[hs4] = cn;
    store_h4(rowoff, hs4, hv);
}

// ---------------------------------------------------------------------------
// Final classifier (reads fp16 h plane)
// ---------------------------------------------------------------------------
__global__ __launch_bounds__(256) void final_k(
    const float* __restrict__ cls_w, const float* __restrict__ cls_b,
    float* __restrict__ out)
{
    const int b  = blockIdx.x;
    const int hs = threadIdx.x;

    const size_t o1 = (size_t)b           * NTREEN * 256 + hs;
    const size_t o2 = (size_t)(b + BATCH) * NTREEN * 256 + hs;

    float s1 = 0.f, s2 = 0.f;
    #pragma unroll 4
    for (int n = 0; n < NTREEN; n++) {
        s1 += __half2float(g_h[o1 + (size_t)n * 256]);
        s2 += __half2float(g_h[o2 + (size_t)n * 256]);
    }
    const float d = fabsf(s1 - s2) * (1.0f / (float)NTREEN);

    float v0 = d * cls_w[hs];
    float v1 = d * cls_w[256 + hs];

    #pragma unroll
    for (int off = 16; off > 0; off >>= 1) {
        v0 += __shfl_down_sync(0xffffffffu, v0, off);
        v1 += __shfl_down_sync(0xffffffffu, v1, off);
    }
    __shared__ float sm0[8], sm1[8];
    const int w = threadIdx.x >> 5, lane = threadIdx.x & 31;
    if (lane == 0) { sm0[w] = v0; sm1[w] = v1; }
    __syncthreads();
    if (threadIdx.x == 0) {
        float t0 = 0.f, t1 = 0.f;
        #pragma unroll
        for (int k = 0; k < 8; k++) { t0 += sm0[k]; t1 += sm1[k]; }
        out[b * 2 + 0] = t0 + cls_b[0];
        out[b * 2 + 1] = t1 + cls_b[1];
    }
}

// ---------------------------------------------------------------------------
// Launch
// ---------------------------------------------------------------------------
extern "C" void kernel_launch(void* const* d_in, const int* in_sizes, int n_in,
                              void* d_out, int out_size)
{
    (void)in_sizes; (void)n_in; (void)out_size;
    const int*   types1 = (const int*)  d_in[0];
    const int*   types2 = (const int*)  d_in[1];
    const float* emb    = (const float*)d_in[2];
    const float* W_iou  = (const float*)d_in[3];
    const float* U_iou  = (const float*)d_in[4];
    const float* b_iou  = (const float*)d_in[5];
    const float* U_f_w  = (const float*)d_in[6];
    const float* U_f_b  = (const float*)d_in[7];
    const float* cls_w  = (const float*)d_in[8];
    const float* cls_b  = (const float*)d_in[9];
    float* out = (float*)d_out;

    cudaFuncSetAttribute(gemm_table, cudaFuncAttributeMaxDynamicSharedMemorySize, T_SMT);
    cudaFuncSetAttribute(gemm_level, cudaFuncAttributeMaxDynamicSharedMemorySize, L_SMT);

    // 0) prep
    split_emb<<<VOCABN, 256>>>(emb);
    split_wt<<<768, 256>>>(W_iou);
    build_wc<<<NPRE, 256>>>(U_iou, U_f_w);

    // 1) vocab table: g_table[v] = W_iou @ emb[v]
    gemm_table<<<dim3(VOCABN / 128, 6), 256, T_SMT>>>();

    // 2) leaves (+ hsum for level 8)
    leaf_ew_pair<<<16384, 256>>>(types1, types2, b_iou);

    // 3) internal levels 8..1 (single-pass fp16 GEMM -> fused ew+hsum)
    for (int lvl = 8; lvl >= 1; --lvl) {
        const int base = (1 << lvl) - 1;
        gemm_level<<<dim3((BTN << lvl) / 128, 10), 256, L_SMT>>>(base);
        level_ew_pair<<<64 << (lvl - 1), 256>>>(b_iou, U_f_b, base);
    }

    // 4) root level
    gemm_level<<<dim3(2, 10), 256, L_SMT>>>(0);
    level_ew_root<<<64, 256>>>(b_iou, U_f_b);

    // 5) classifier
    final_k<<<BATCH, 256>>>(cls_w, cls_b, out);
}

// round 12
// speedup vs baseline: 1.8563x; 1.0957x over previous
#include <cuda_runtime.h>
#include <cuda_fp16.h>
#include <stdint.h>
#include <math.h>

// ---------------------------------------------------------------------------
// Problem constants
// ---------------------------------------------------------------------------
#define VOCABN 32000
#define BATCH  128
#define BTN    256          // 2*BATCH
#define NTREEN 1023
#define NPRE   1280         // iou(768) | f0(256) | f1(256)

// ---------------------------------------------------------------------------
// Scratch (device globals) — everything bandwidth-critical in fp16;
// c (recurrent accumulator), biases, final reduction in fp32.
// ---------------------------------------------------------------------------
__device__ __align__(16) __half g_emb  [(size_t)VOCABN * 256];
__device__ __align__(16) __half g_Wt   [768 * 256];
__device__ __align__(16) __half g_Wc   [NPRE * 256];
__device__ __align__(16) __half g_table[(size_t)VOCABN * 768];
__device__ __align__(16) __half g_h    [(size_t)BTN * NTREEN * 256];
__device__ __align__(16) __half g_hsum [(size_t)65536 * 256];
__device__ __align__(16) __half g_pre  [(size_t)65536 * NPRE];
__device__ __align__(16) float  g_c    [(size_t)BTN * NTREEN * 256];

// ---------------------------------------------------------------------------
// Helpers
// ---------------------------------------------------------------------------
__device__ __forceinline__ float sigf(float x)   { return 1.0f / (1.0f + __expf(-x)); }
__device__ __forceinline__ float tanhf_(float x) { return 2.0f / (1.0f + __expf(-2.0f * x)) - 1.0f; }

__device__ __forceinline__ uint32_t smem_u32(const void* p) {
    uint32_t a;
    asm("{ .reg .u64 t; cvta.to.shared.u64 t, %1; cvt.u32.u64 %0, t; }" : "=r"(a) : "l"(p));
    return a;
}

// read 4 consecutive fp16 at half2-aligned offset -> float4
__device__ __forceinline__ float4 ldh4(const __half2* p) {
    __half2 a = p[0], b = p[1];
    return make_float4(__low2float(a), __high2float(a),
                       __low2float(b), __high2float(b));
}

// ---------------------------------------------------------------------------
// Baseline-PTX tensor ops + cp.async
// ---------------------------------------------------------------------------
__device__ __forceinline__ void ldm_x4(uint32_t r[4], uint32_t addr) {
    asm volatile("ldmatrix.sync.aligned.m8n8.x4.shared.b16 {%0,%1,%2,%3}, [%4];"
        : "=r"(r[0]), "=r"(r[1]), "=r"(r[2]), "=r"(r[3]) : "r"(addr));
}
__device__ __forceinline__ void ldm_x2(uint32_t r[2], uint32_t addr) {
    asm volatile("ldmatrix.sync.aligned.m8n8.x2.shared.b16 {%0,%1}, [%2];"
        : "=r"(r[0]), "=r"(r[1]) : "r"(addr));
}
__device__ __forceinline__ void mma_f16(float c[4], const uint32_t a[4], const uint32_t b[2]) {
    asm volatile("mma.sync.aligned.m16n8k16.row.col.f32.f16.f16.f32 "
        "{%0,%1,%2,%3}, {%4,%5,%6,%7}, {%8,%9}, {%0,%1,%2,%3};"
        : "+f"(c[0]), "+f"(c[1]), "+f"(c[2]), "+f"(c[3])
        : "r"(a[0]), "r"(a[1]), "r"(a[2]), "r"(a[3]), "r"(b[0]), "r"(b[1]));
}
#define CP16(dst, src) asm volatile("cp.async.cg.shared.global [%0], [%1], 16;" :: "r"(dst), "l"(src))
#define CP_COMMIT()    asm volatile("cp.async.commit_group;" ::: "memory")
#define CP_WAIT0()     asm volatile("cp.async.wait_group 0;" ::: "memory")

// ---------------------------------------------------------------------------
// Prep kernels (device globals referenced from device code only)
// ---------------------------------------------------------------------------
__global__ __launch_bounds__(256) void emb_f16(const float* __restrict__ src)
{
    const int idx = blockIdx.x * 256 + threadIdx.x;
    g_emb[idx] = __float2half_rn(src[idx]);
}
__global__ __launch_bounds__(256) void wt_f16(const float* __restrict__ src)
{
    const int idx = blockIdx.x * 256 + threadIdx.x;
    g_Wt[idx] = __float2half_rn(src[idx]);
}
// Wc rows: [0:768)=U_iou, [768:1024)=U_f_w, [1024:1280)=U_f_w
__global__ __launch_bounds__(256) void build_wc(
    const float* __restrict__ U_iou, const float* __restrict__ U_f_w)
{
    const int idx = blockIdx.x * 256 + threadIdx.x;
    const int n = idx >> 8, k = idx & 255;
    const float v = (n < 768) ? U_iou[n * 256 + k]
                              : U_f_w[((n - 768) & 255) * 256 + k];
    g_Wc[idx] = __float2half_rn(v);
}

// ---------------------------------------------------------------------------
// Single-pass fp16 GEMM core.  C[M,N](fp16) = A[M,256] @ B[N,256]^T
// CTA tile 128x128, K = 4x64, smem A 16K | B 16K = 32K, 2 CTA/SM.
// MODE 0 (table): A = g_emb, B = g_Wt, C = g_table (Nc=768, 6 n-tiles)
// MODE 1 (level): tiles 0-5: A = hsum | 6,7: child0 | 8,9: child1
//                 B = g_Wc, C = g_pre (Nc=1280)
// ---------------------------------------------------------------------------
#define L_SM_A 0u
#define L_SM_B 16384u
#define L_SMT  32768

template<int MODE>
__global__ __launch_bounds__(256, 2) void gemm_f16(int base)
{
    extern __shared__ char smem[];
    const uint32_t sb = smem_u32(smem);
    const int tid = threadIdx.x, wid = tid >> 5, lane = tid & 31;
    const int bm = blockIdx.x * 128;
    const int tile = blockIdx.y;
    const int bn = tile * 128;
    const int Nc = (MODE == 0) ? 768 : NPRE;

    // A source (fp16 plane)
    const __half* a;
    {
        const int r = bm + (tid >> 1);
        if (MODE == 0) {
            a = g_emb + (size_t)r * 256;
        } else if (tile < 6) {
            a = g_hsum + (size_t)r * 256;
        } else {
            const int s = (tile - 6) >> 1;
            const int j = r >> 8, bt = r & 255, node = base + j;
            a = g_h + ((size_t)bt * NTREEN + 2 * node + 1 + s) * 256;
        }
        a += (tid & 1) * 32;
    }
    const __half* b = ((MODE == 0) ? g_Wt : g_Wc)
                      + (size_t)(bn + (tid >> 1)) * 256 + (tid & 1) * 32;

    const uint32_t rowoff = (uint32_t)(tid >> 1) * 128u;
    const uint32_t rxor   = (uint32_t)(((tid >> 1) & 7) << 4);

    const int wm = (wid & 1) * 64;
    const int wn = (wid >> 1) * 32;
    float acc[4][4][4] = {};

    #pragma unroll 1
    for (int kc = 0; kc < 4; kc++) {
        const int k0 = kc * 64;
        #pragma unroll
        for (int j = 0; j < 4; j++) {
            const uint32_t xo = (uint32_t)((tid & 1) * 64 + j * 16) ^ rxor;
            const uint32_t d = rowoff + xo;
            CP16(sb + L_SM_A + d, a + k0 + j * 8);
            CP16(sb + L_SM_B + d, b + k0 + j * 8);
        }
        CP_COMMIT();
        CP_WAIT0();
        __syncthreads();

        #pragma unroll
        for (int kg = 0; kg < 4; kg++) {
            uint32_t bf[4][2];
            #pragma unroll
            for (int nf = 0; nf < 4; nf++) {
                const uint32_t nrow = (uint32_t)(wn + nf * 8 + (lane & 7));
                const uint32_t x = (uint32_t)(kg * 32 + ((lane >> 3) & 1) * 16);
                const uint32_t sw = nrow * 128u + (x ^ ((nrow & 7u) << 4));
                ldm_x2(bf[nf], sb + L_SM_B + sw);
            }
            #pragma unroll
            for (int mf = 0; mf < 4; mf++) {
                const uint32_t mrow = (uint32_t)(wm + mf * 16 + (lane & 15));
                const uint32_t x = (uint32_t)(kg * 32 + (lane >> 4) * 16);
                const uint32_t sw = mrow * 128u + (x ^ ((mrow & 7u) << 4));
                uint32_t a4[4];
                ldm_x4(a4, sb + L_SM_A + sw);
                #pragma unroll
                for (int nf = 0; nf < 4; nf++)
                    mma_f16(acc[mf][nf], a4, bf[nf]);
            }
        }
        __syncthreads();
    }

    // ---- epilogue: fp16 output ----
    __half* __restrict__ C = (MODE == 0) ? g_table : g_pre;
    #pragma unroll
    for (int mf = 0; mf < 4; mf++) {
        const int row = bm + wm + mf * 16 + (lane >> 2);
        #pragma unroll
        for (int nf = 0; nf < 4; nf++) {
            const int col = bn + wn + nf * 8 + (lane & 3) * 2;
            *(__half2*)&C[(size_t)row * Nc + col] =
                __floats2half2_rn(acc[mf][nf][0], acc[mf][nf][1]);
            *(__half2*)&C[(size_t)(row + 8) * Nc + col] =
                __floats2half2_rn(acc[mf][nf][2], acc[mf][nf][3]);
        }
    }
}

// ---------------------------------------------------------------------------
// h / hsum store helpers: fp32 -> fp16
// ---------------------------------------------------------------------------
__device__ __forceinline__ void store_h4(size_t rowoff, int hs4, const float h[4]) {
    unsigned short b[4];
    #pragma unroll
    for (int e = 0; e < 4; e++) b[e] = __half_as_ushort(__float2half_rn(h[e]));
    ((uint2*)(g_h + rowoff))[hs4] =
        make_uint2(b[0] | ((unsigned)b[1] << 16), b[2] | ((unsigned)b[3] << 16));
}
__device__ __forceinline__ void store_hsum4(size_t rowoff, int hs4, const float h[4]) {
    unsigned short b[4];
    #pragma unroll
    for (int e = 0; e < 4; e++) b[e] = __half_as_ushort(__float2half_rn(h[e]));
    ((uint2*)(g_hsum + rowoff))[hs4] =
        make_uint2(b[0] | ((unsigned)b[1] << 16), b[2] | ((unsigned)b[3] << 16));
}

// ---------------------------------------------------------------------------
// Leaf elementwise, fused sibling pair + hsum (fp16 table).
// ---------------------------------------------------------------------------
__global__ __launch_bounds__(256) void leaf_ew_pair(
    const int* __restrict__ types1, const int* __restrict__ types2,
    const float* __restrict__ b_iou)
{
    const int tid = blockIdx.x * 256 + threadIdx.x;
    const int hs4 = tid & 63;
    const int q   = tid >> 6;            // 0 .. 256*256-1
    const int bt  = q & 255;
    const int tp  = q >> 8;              // pair 0..255

    const int* ty = (bt < BATCH) ? types1 + bt * NTREEN
                                 : types2 + (bt - BATCH) * NTREEN;
    const float4* bb = (const float4*)b_iou;
    const float4 b0 = bb[hs4], b1 = bb[64 + hs4], b2 = bb[128 + hs4];

    float hsum[4] = {0.f, 0.f, 0.f, 0.f};
    #pragma unroll
    for (int s = 0; s < 2; s++) {
        const int node = 511 + 2 * tp + s;
        const int v = ty[node];
        const __half2* t2 = (const __half2*)(g_table + (size_t)v * 768);
        const float4 i4 = ldh4(t2 + hs4 * 2);
        const float4 o4 = ldh4(t2 + 128 + hs4 * 2);
        const float4 u4 = ldh4(t2 + 256 + hs4 * 2);

        float4 cn; float hv[4];
        #define DOLANE(c_, e_)                                       \
        {   float cv = sigf(i4.c_ + b0.c_) * tanhf_(u4.c_ + b2.c_);  \
            cn.c_ = cv;                                              \
            hv[e_] = sigf(o4.c_ + b1.c_) * tanhf_(cv);               \
            hsum[e_] += hv[e_]; }
        DOLANE(x, 0) DOLANE(y, 1) DOLANE(z, 2) DOLANE(w, 3)
        #undef DOLANE

        const size_t rowoff = ((size_t)bt * NTREEN + node) * 256;
        ((float4*)(g_c + rowoff))[hs4] = cn;
        store_h4(rowoff, hs4, hv);
    }
    store_hsum4((size_t)(tp * 256 + bt) * 256, hs4, hsum);
}

// ---------------------------------------------------------------------------
// Internal-level elementwise, fused sibling pair + hsum (fp16 pre).
// ---------------------------------------------------------------------------
__global__ __launch_bounds__(256) void level_ew_pair(
    const float* __restrict__ b_iou, const float* __restrict__ U_f_b, int cbase)
{
    const int tid = blockIdx.x * 256 + threadIdx.x;
    const int hs4 = tid & 63;
    const int q   = tid >> 6;
    const int bt  = q & 255;
    const int tp  = q >> 8;

    const float4* bb = (const float4*)b_iou;
    const float4 b0 = bb[hs4], b1 = bb[64 + hs4], b2 = bb[128 + hs4];
    const float4 fb = ((const float4*)U_f_b)[hs4];

    float hsum[4] = {0.f, 0.f, 0.f, 0.f};
    #pragma unroll
    for (int s = 0; s < 2; s++) {
        const int node = cbase + 2 * tp + s;
        const int i    = (2 * tp + s) * 256 + bt;

        const size_t rc0 = ((size_t)bt * NTREEN + 2 * node + 1) * 256;
        const float4 c0 = ((const float4*)(g_c + rc0))[hs4];
        const float4 c1 = ((const float4*)(g_c + rc0 + 256))[hs4];

        const __half2* p2 = (const __half2*)(g_pre + (size_t)i * NPRE);
        const float4 iI = ldh4(p2 + hs4 * 2);
        const float4 iO = ldh4(p2 + 128 + hs4 * 2);
        const float4 iU = ldh4(p2 + 256 + hs4 * 2);
        const float4 f0 = ldh4(p2 + 384 + hs4 * 2);
        const float4 f1 = ldh4(p2 + 512 + hs4 * 2);

        float4 cn; float hv[4];
        #define DOLANE(c_, e_)                                                      \
        {   float csum = sigf(f0.c_ + fb.c_) * c0.c_ + sigf(f1.c_ + fb.c_) * c1.c_; \
            float cv = sigf(iI.c_ + b0.c_) * tanhf_(iU.c_ + b2.c_) + csum;          \
            cn.c_ = cv;                                                             \
            hv[e_] = sigf(iO.c_ + b1.c_) * tanhf_(cv);                              \
            hsum[e_] += hv[e_]; }
        DOLANE(x, 0) DOLANE(y, 1) DOLANE(z, 2) DOLANE(w, 3)
        #undef DOLANE

        const size_t rowoff = ((size_t)bt * NTREEN + node) * 256;
        ((float4*)(g_c + rowoff))[hs4] = cn;
        store_h4(rowoff, hs4, hv);
    }
    store_hsum4((size_t)(tp * 256 + bt) * 256, hs4, hsum);
}

// ---------------------------------------------------------------------------
// Root elementwise (node 0, no hsum)
// ---------------------------------------------------------------------------
__global__ __launch_bounds__(256) void level_ew_root(
    const float* __restrict__ b_iou, const float* __restrict__ U_f_b)
{
    const int tid = blockIdx.x * 256 + threadIdx.x;
    const int hs4 = tid & 63;
    const int bt  = tid >> 6;            // 0..255

    const size_t rc0 = ((size_t)bt * NTREEN + 1) * 256;
    const float4 c0 = ((const float4*)(g_c + rc0))[hs4];
    const float4 c1 = ((const float4*)(g_c + rc0 + 256))[hs4];

    const __half2* p2 = (const __half2*)(g_pre + (size_t)bt * NPRE);
    const float4 iI = ldh4(p2 + hs4 * 2);
    const float4 iO = ldh4(p2 + 128 + hs4 * 2);
    const float4 iU = ldh4(p2 + 256 + hs4 * 2);
    const float4 f0 = ldh4(p2 + 384 + hs4 * 2);
    const float4 f1 = ldh4(p2 + 512 + hs4 * 2);

    const float4* bb = (const float4*)b_iou;
    const float4 b0 = bb[hs4], b1 = bb[64 + hs4], b2 = bb[128 + hs4];
    const float4 fb = ((const float4*)U_f_b)[hs4];

    float4 cn; float hv[4];
    #define DOLANE(c_, e_)                                                      \
    {   float csum = sigf(f0.c_ + fb.c_) * c0.c_ + sigf(f1.c_ + fb.c_) * c1.c_; \
        float cv = sigf(iI.c_ + b0.c_) * tanhf_(iU.c_ + b2.c_) + csum;          \
        cn.c_ = cv;                                                             \
        hv[e_] = sigf(iO.c_ + b1.c_) * tanhf_(cv); }
    DOLANE(x, 0) DOLANE(y, 1) DOLANE(z, 2) DOLANE(w, 3)
    #undef DOLANE

    const size_t rowoff = (size_t)bt * NTREEN * 256;
    ((float4*)(g_c + rowoff))[hs4] = cn;
    store_h4(rowoff, hs4, hv);
}

// ---------------------------------------------------------------------------
// Final classifier (fp16 h plane, fp32 accumulation)
// ---------------------------------------------------------------------------
__global__ __launch_bounds__(256) void final_k(
    const float* __restrict__ cls_w, const float* __restrict__ cls_b,
    float* __restrict__ out)
{
    const int b  = blockIdx.x;
    const int hs = threadIdx.x;

    const size_t o1 = (size_t)b           * NTREEN * 256 + hs;
    const size_t o2 = (size_t)(b + BATCH) * NTREEN * 256 + hs;

    float s1 = 0.f, s2 = 0.f;
    #pragma unroll 4
    for (int n = 0; n < NTREEN; n++) {
        s1 += __half2float(g_h[o1 + (size_t)n * 256]);
        s2 += __half2float(g_h[o2 + (size_t)n * 256]);
    }
    const float d = fabsf(s1 - s2) * (1.0f / (float)NTREEN);

    float v0 = d * cls_w[hs];
    float v1 = d * cls_w[256 + hs];

    #pragma unroll
    for (int off = 16; off > 0; off >>= 1) {
        v0 += __shfl_down_sync(0xffffffffu, v0, off);
        v1 += __shfl_down_sync(0xffffffffu, v1, off);
    }
    __shared__ float sm0[8], sm1[8];
    const int w = threadIdx.x >> 5, lane = threadIdx.x & 31;
    if (lane == 0) { sm0[w] = v0; sm1[w] = v1; }
    __syncthreads();
    if (threadIdx.x == 0) {
        float t0 = 0.f, t1 = 0.f;
        #pragma unroll
        for (int k = 0; k < 8; k++) { t0 += sm0[k]; t1 += sm1[k]; }
        out[b * 2 + 0] = t0 + cls_b[0];
        out[b * 2 + 1] = t1 + cls_b[1];
    }
}

// ---------------------------------------------------------------------------
// Launch
// ---------------------------------------------------------------------------
extern "C" void kernel_launch(void* const* d_in, const int* in_sizes, int n_in,
                              void* d_out, int out_size)
{
    (void)in_sizes; (void)n_in; (void)out_size;
    const int*   types1 = (const int*)  d_in[0];
    const int*   types2 = (const int*)  d_in[1];
    const float* emb    = (const float*)d_in[2];
    const float* W_iou  = (const float*)d_in[3];
    const float* U_iou  = (const float*)d_in[4];
    const float* b_iou  = (const float*)d_in[5];
    const float* U_f_w  = (const float*)d_in[6];
    const float* U_f_b  = (const float*)d_in[7];
    const float* cls_w  = (const float*)d_in[8];
    const float* cls_b  = (const float*)d_in[9];
    float* out = (float*)d_out;

    cudaFuncSetAttribute(gemm_f16<0>, cudaFuncAttributeMaxDynamicSharedMemorySize, L_SMT);
    cudaFuncSetAttribute(gemm_f16<1>, cudaFuncAttributeMaxDynamicSharedMemorySize, L_SMT);

    // 0) prep: fp16 conversions
    emb_f16<<<VOCABN, 256>>>(emb);
    wt_f16<<<768, 256>>>(W_iou);
    build_wc<<<NPRE, 256>>>(U_iou, U_f_w);

    // 1) vocab table: g_table[v] = W_iou @ emb[v]   (fp16 single-pass)
    gemm_f16<0><<<dim3(VOCABN / 128, 6), 256, L_SMT>>>(0);

    // 2) leaves (+ hsum for level 8)
    leaf_ew_pair<<<16384, 256>>>(types1, types2, b_iou);

    // 3) internal levels 8..1 (fp16 GEMM -> fused ew+hsum)
    for (int lvl = 8; lvl >= 1; --lvl) {
        const int base = (1 << lvl) - 1;
        gemm_f16<1><<<dim3((BTN << lvl) / 128, 10), 256, L_SMT>>>(base);
        level_ew_pair<<<64 << (lvl - 1), 256>>>(b_iou, U_f_b, base);
    }

    // 4) root level
    gemm_f16<1><<<dim3(2, 10), 256, L_SMT>>>(0);
    level_ew_root<<<64, 256>>>(b_iou, U_f_b);

    // 5) classifier
    final_k<<<BATCH, 256>>>(cls_w, cls_b, out);
}

// round 13
// speedup vs baseline: 1.9897x; 1.0719x over previous
#include <cuda_runtime.h>
#include <cuda_fp16.h>
#include <stdint.h>
#include <math.h>

// ---------------------------------------------------------------------------
// Problem constants
// ---------------------------------------------------------------------------
#define VOCABN 32000
#define BATCH  128
#define BTN    256          // 2*BATCH
#define NTREEN 1023
#define NPRE   1280         // iou(768) | f0(256) | f1(256)

// ---------------------------------------------------------------------------
// Scratch (device globals)
// ---------------------------------------------------------------------------
__device__ __align__(16) __half g_emb  [(size_t)VOCABN * 256];
__device__ __align__(16) __half g_Wt   [768 * 256];
__device__ __align__(16) __half g_Wc   [NPRE * 256];
__device__ __align__(16) __half g_table[(size_t)VOCABN * 768];
__device__ __align__(16) __half g_hleaf[(size_t)VOCABN * 256];   // leaf h per vocab
__device__ __align__(16) float  g_cleaf[(size_t)VOCABN * 256];   // leaf c per vocab
__device__ __align__(16) __half g_h    [(size_t)BTN * NTREEN * 256];
__device__ __align__(16) __half g_hsum [(size_t)65536 * 256];
__device__ __align__(16) __half g_pre  [(size_t)65536 * NPRE];
__device__ __align__(16) float  g_c    [(size_t)BTN * NTREEN * 256];

// ---------------------------------------------------------------------------
// Helpers
// ---------------------------------------------------------------------------
__device__ __forceinline__ float sigf(float x)   { return 1.0f / (1.0f + __expf(-x)); }
__device__ __forceinline__ float tanhf_(float x) { return 2.0f / (1.0f + __expf(-2.0f * x)) - 1.0f; }

__device__ __forceinline__ uint32_t smem_u32(const void* p) {
    uint32_t a;
    asm("{ .reg .u64 t; cvta.to.shared.u64 t, %1; cvt.u32.u64 %0, t; }" : "=r"(a) : "l"(p));
    return a;
}
__device__ __forceinline__ float4 ldh4(const __half2* p) {
    __half2 a = p[0], b = p[1];
    return make_float4(__low2float(a), __high2float(a),
                       __low2float(b), __high2float(b));
}

// ---------------------------------------------------------------------------
// Baseline-PTX tensor ops + cp.async
// ---------------------------------------------------------------------------
__device__ __forceinline__ void ldm_x4(uint32_t r[4], uint32_t addr) {
    asm volatile("ldmatrix.sync.aligned.m8n8.x4.shared.b16 {%0,%1,%2,%3}, [%4];"
        : "=r"(r[0]), "=r"(r[1]), "=r"(r[2]), "=r"(r[3]) : "r"(addr));
}
__device__ __forceinline__ void ldm_x2(uint32_t r[2], uint32_t addr) {
    asm volatile("ldmatrix.sync.aligned.m8n8.x2.shared.b16 {%0,%1}, [%2];"
        : "=r"(r[0]), "=r"(r[1]) : "r"(addr));
}
__device__ __forceinline__ void mma_f16(float c[4], const uint32_t a[4], const uint32_t b[2]) {
    asm volatile("mma.sync.aligned.m16n8k16.row.col.f32.f16.f16.f32 "
        "{%0,%1,%2,%3}, {%4,%5,%6,%7}, {%8,%9}, {%0,%1,%2,%3};"
        : "+f"(c[0]), "+f"(c[1]), "+f"(c[2]), "+f"(c[3])
        : "r"(a[0]), "r"(a[1]), "r"(a[2]), "r"(a[3]), "r"(b[0]), "r"(b[1]));
}
#define CP16(dst, src) asm volatile("cp.async.cg.shared.global [%0], [%1], 16;" :: "r"(dst), "l"(src))
#define CP_COMMIT()    asm volatile("cp.async.commit_group;" ::: "memory")
#define CP_WAIT1()     asm volatile("cp.async.wait_group 1;" ::: "memory")
#define CP_WAIT0()     asm volatile("cp.async.wait_group 0;" ::: "memory")

// ---------------------------------------------------------------------------
// Prep kernels
// ---------------------------------------------------------------------------
__global__ __launch_bounds__(256) void emb_f16(const float* __restrict__ src)
{
    const int idx = blockIdx.x * 256 + threadIdx.x;
    g_emb[idx] = __float2half_rn(src[idx]);
}
__global__ __launch_bounds__(256) void wt_f16(const float* __restrict__ src)
{
    const int idx = blockIdx.x * 256 + threadIdx.x;
    g_Wt[idx] = __float2half_rn(src[idx]);
}
__global__ __launch_bounds__(256) void build_wc(
    const float* __restrict__ U_iou, const float* __restrict__ U_f_w)
{
    const int idx = blockIdx.x * 256 + threadIdx.x;
    const int n = idx >> 8, k = idx & 255;
    const float v = (n < 768) ? U_iou[n * 256 + k]
                              : U_f_w[((n - 768) & 255) * 256 + k];
    g_Wc[idx] = __float2half_rn(v);
}

// ---------------------------------------------------------------------------
// Double-buffered single-pass fp16 GEMM.  C[M,N](fp16) = A[M,256] @ B[N,256]^T
// CTA tile 128x128, K = 4 chunks of 64, 2 stages x 32KB = 64KB, 2 CTA/SM.
// MODE 0 (table): A = g_emb, B = g_Wt, C = g_table (Nc=768, 6 n-tiles)
// MODE 1 (level): tiles 0-5: A = hsum | 6,7: child0 | 8,9: child1
//                 B = g_Wc, C = g_pre (Nc=1280)
// ---------------------------------------------------------------------------
#define SM_A  0u
#define SM_B  16384u
#define STGS  32768u
#define L_SMT 65536

template<int MODE>
__global__ __launch_bounds__(256, 2) void gemm_f16(int base)
{
    extern __shared__ char smem[];
    const uint32_t sb = smem_u32(smem);
    const int tid = threadIdx.x, wid = tid >> 5, lane = tid & 31;
    const int bm = blockIdx.x * 128;
    const int tile = blockIdx.y;
    const int bn = tile * 128;
    const int Nc = (MODE == 0) ? 768 : NPRE;

    // A source (fp16 plane)
    const __half* a;
    {
        const int r = bm + (tid >> 1);
        if (MODE == 0) {
            a = g_emb + (size_t)r * 256;
        } else if (tile < 6) {
            a = g_hsum + (size_t)r * 256;
        } else {
            const int s = (tile - 6) >> 1;
            const int j = r >> 8, bt = r & 255, node = base + j;
            a = g_h + ((size_t)bt * NTREEN + 2 * node + 1 + s) * 256;
        }
        a += (tid & 1) * 32;
    }
    const __half* b = ((MODE == 0) ? g_Wt : g_Wc)
                      + (size_t)(bn + (tid >> 1)) * 256 + (tid & 1) * 32;

    const uint32_t rowoff = (uint32_t)(tid >> 1) * 128u;
    const uint32_t rxor   = (uint32_t)(((tid >> 1) & 7) << 4);

    #define LOADC(s, k0) do {                                                  \
        const uint32_t st_ = sb + (uint32_t)(s) * STGS;                        \
        _Pragma("unroll")                                                      \
        for (int j = 0; j < 4; j++) {                                          \
            const uint32_t xo = (uint32_t)((tid & 1) * 64 + j * 16) ^ rxor;    \
            const uint32_t d = rowoff + xo;                                    \
            CP16(st_ + SM_A + d, a + (k0) + j * 8);                            \
            CP16(st_ + SM_B + d, b + (k0) + j * 8);                            \
        }                                                                      \
    } while (0)

    const int wm = (wid & 1) * 64;
    const int wn = (wid >> 1) * 32;
    float acc[4][4][4] = {};

    LOADC(0, 0);
    CP_COMMIT();

    #pragma unroll 1
    for (int kc = 0; kc < 4; kc++) {
        if (kc < 3) {
            LOADC((kc + 1) & 1, (kc + 1) * 64);
            CP_COMMIT();
            CP_WAIT1();
        } else {
            CP_WAIT0();
        }
        __syncthreads();

        const uint32_t st = sb + (uint32_t)(kc & 1) * STGS;
        #pragma unroll
        for (int kg = 0; kg < 4; kg++) {
            uint32_t bf[4][2];
            #pragma unroll
            for (int nf = 0; nf < 4; nf++) {
                const uint32_t nrow = (uint32_t)(wn + nf * 8 + (lane & 7));
                const uint32_t x = (uint32_t)(kg * 32 + ((lane >> 3) & 1) * 16);
                const uint32_t sw = nrow * 128u + (x ^ ((nrow & 7u) << 4));
                ldm_x2(bf[nf], st + SM_B + sw);
            }
            #pragma unroll
            for (int mf = 0; mf < 4; mf++) {
                const uint32_t mrow = (uint32_t)(wm + mf * 16 + (lane & 15));
                const uint32_t x = (uint32_t)(kg * 32 + (lane >> 4) * 16);
                const uint32_t sw = mrow * 128u + (x ^ ((mrow & 7u) << 4));
                uint32_t a4[4];
                ldm_x4(a4, st + SM_A + sw);
                #pragma unroll
                for (int nf = 0; nf < 4; nf++)
                    mma_f16(acc[mf][nf], a4, bf[nf]);
            }
        }
        __syncthreads();
    }
    #undef LOADC

    __half* __restrict__ C = (MODE == 0) ? g_table : g_pre;
    #pragma unroll
    for (int mf = 0; mf < 4; mf++) {
        const int row = bm + wm + mf * 16 + (lane >> 2);
        #pragma unroll
        for (int nf = 0; nf < 4; nf++) {
            const int col = bn + wn + nf * 8 + (lane & 3) * 2;
            *(__half2*)&C[(size_t)row * Nc + col] =
                __floats2half2_rn(acc[mf][nf][0], acc[mf][nf][1]);
            *(__half2*)&C[(size_t)(row + 8) * Nc + col] =
                __floats2half2_rn(acc[mf][nf][2], acc[mf][nf][3]);
        }
    }
}

// ---------------------------------------------------------------------------
// fp16 store helpers
// ---------------------------------------------------------------------------
__device__ __forceinline__ uint2 pack_h4(const float h[4]) {
    unsigned short b[4];
    #pragma unroll
    for (int e = 0; e < 4; e++) b[e] = __half_as_ushort(__float2half_rn(h[e]));
    return make_uint2(b[0] | ((unsigned)b[1] << 16), b[2] | ((unsigned)b[3] << 16));
}

// ---------------------------------------------------------------------------
// Vocab leaf precompute: for each vocab id, h_leaf / c_leaf from table + b_iou.
// 32000 rows (vs 131072 leaf instances) -> 4x less activation math.
// ---------------------------------------------------------------------------
__global__ __launch_bounds__(256) void vocab_leaf(const float* __restrict__ b_iou)
{
    const int t   = blockIdx.x * 256 + threadIdx.x;  // 0 .. 32000*64-1
    const int hs4 = t & 63;
    const int v   = t >> 6;

    const float4* bb = (const float4*)b_iou;
    const float4 b0 = bb[hs4], b1 = bb[64 + hs4], b2 = bb[128 + hs4];

    const __half2* t2 = (const __half2*)(g_table + (size_t)v * 768);
    const float4 i4 = ldh4(t2 + hs4 * 2);
    const float4 o4 = ldh4(t2 + 128 + hs4 * 2);
    const float4 u4 = ldh4(t2 + 256 + hs4 * 2);

    float4 cn; float hv[4];
    #define DOLANE(c_, e_)                                       \
    {   float cv = sigf(i4.c_ + b0.c_) * tanhf_(u4.c_ + b2.c_);  \
        cn.c_ = cv;                                              \
        hv[e_] = sigf(o4.c_ + b1.c_) * tanhf_(cv); }
    DOLANE(x, 0) DOLANE(y, 1) DOLANE(z, 2) DOLANE(w, 3)
    #undef DOLANE

    ((float4*)(g_cleaf + (size_t)v * 256))[hs4] = cn;
    ((uint2*)(g_hleaf + (size_t)v * 256))[hs4]  = pack_h4(hv);
}

// ---------------------------------------------------------------------------
// Leaf gather: copy per-vocab h/c into tree slots + sibling hsum. Pure BW.
// ---------------------------------------------------------------------------
__global__ __launch_bounds__(256) void leaf_gather(
    const int* __restrict__ types1, const int* __restrict__ types2)
{
    const int tid = blockIdx.x * 256 + threadIdx.x;
    const int hs4 = tid & 63;
    const int q   = tid >> 6;
    const int bt  = q & 255;
    const int tp  = q >> 8;              // pair 0..255

    const int* ty = (bt < BATCH) ? types1 + bt * NTREEN
                                 : types2 + (bt - BATCH) * NTREEN;

    float hsum[4] = {0.f, 0.f, 0.f, 0.f};
    #pragma unroll
    for (int s = 0; s < 2; s++) {
        const int node = 511 + 2 * tp + s;
        const int v = ty[node];

        const uint2  hp = ((const uint2*)(g_hleaf + (size_t)v * 256))[hs4];
        const float4 cp = ((const float4*)(g_cleaf + (size_t)v * 256))[hs4];

        hsum[0] += __half2float(__ushort_as_half((unsigned short)(hp.x & 0xFFFF)));
        hsum[1] += __half2float(__ushort_as_half((unsigned short)(hp.x >> 16)));
        hsum[2] += __half2float(__ushort_as_half((unsigned short)(hp.y & 0xFFFF)));
        hsum[3] += __half2float(__ushort_as_half((unsigned short)(hp.y >> 16)));

        const size_t rowoff = ((size_t)bt * NTREEN + node) * 256;
        ((uint2*)(g_h + rowoff))[hs4]  = hp;
        ((float4*)(g_c + rowoff))[hs4] = cp;
    }
    ((uint2*)(g_hsum + (size_t)(tp * 256 + bt) * 256))[hs4] = pack_h4(hsum);
}

// ---------------------------------------------------------------------------
// Internal-level elementwise, fused sibling pair + hsum (fp16 pre).
// ---------------------------------------------------------------------------
__global__ __launch_bounds__(256) void level_ew_pair(
    const float* __restrict__ b_iou, const float* __restrict__ U_f_b, int cbase)
{
    const int tid = blockIdx.x * 256 + threadIdx.x;
    const int hs4 = tid & 63;
    const int q   = tid >> 6;
    const int bt  = q & 255;
    const int tp  = q >> 8;

    const float4* bb = (const float4*)b_iou;
    const float4 b0 = bb[hs4], b1 = bb[64 + hs4], b2 = bb[128 + hs4];
    const float4 fb = ((const float4*)U_f_b)[hs4];

    float hsum[4] = {0.f, 0.f, 0.f, 0.f};
    #pragma unroll
    for (int s = 0; s < 2; s++) {
        const int node = cbase + 2 * tp + s;
        const int i    = (2 * tp + s) * 256 + bt;

        const size_t rc0 = ((size_t)bt * NTREEN + 2 * node + 1) * 256;
        const float4 c0 = ((const float4*)(g_c + rc0))[hs4];
        const float4 c1 = ((const float4*)(g_c + rc0 + 256))[hs4];

        const __half2* p2 = (const __half2*)(g_pre + (size_t)i * NPRE);
        const float4 iI = ldh4(p2 + hs4 * 2);
        const float4 iO = ldh4(p2 + 128 + hs4 * 2);
        const float4 iU = ldh4(p2 + 256 + hs4 * 2);
        const float4 f0 = ldh4(p2 + 384 + hs4 * 2);
        const float4 f1 = ldh4(p2 + 512 + hs4 * 2);

        float4 cn; float hv[4];
        #define DOLANE(c_, e_)                                                      \
        {   float csum = sigf(f0.c_ + fb.c_) * c0.c_ + sigf(f1.c_ + fb.c_) * c1.c_; \
            float cv = sigf(iI.c_ + b0.c_) * tanhf_(iU.c_ + b2.c_) + csum;          \
            cn.c_ = cv;                                                             \
            hv[e_] = sigf(iO.c_ + b1.c_) * tanhf_(cv);                              \
            hsum[e_] += hv[e_]; }
        DOLANE(x, 0) DOLANE(y, 1) DOLANE(z, 2) DOLANE(w, 3)
        #undef DOLANE

        const size_t rowoff = ((size_t)bt * NTREEN + node) * 256;
        ((float4*)(g_c + rowoff))[hs4] = cn;
        ((uint2*)(g_h + rowoff))[hs4]  = pack_h4(hv);
    }
    ((uint2*)(g_hsum + (size_t)(tp * 256 + bt) * 256))[hs4] = pack_h4(hsum);
}

// ---------------------------------------------------------------------------
// Root elementwise (node 0, no hsum)
// ---------------------------------------------------------------------------
__global__ __launch_bounds__(256) void level_ew_root(
    const float* __restrict__ b_iou, const float* __restrict__ U_f_b)
{
    const int tid = blockIdx.x * 256 + threadIdx.x;
    const int hs4 = tid & 63;
    const int bt  = tid >> 6;

    const size_t rc0 = ((size_t)bt * NTREEN + 1) * 256;
    const float4 c0 = ((const float4*)(g_c + rc0))[hs4];
    const float4 c1 = ((const float4*)(g_c + rc0 + 256))[hs4];

    const __half2* p2 = (const __half2*)(g_pre + (size_t)bt * NPRE);
    const float4 iI = ldh4(p2 + hs4 * 2);
    const float4 iO = ldh4(p2 + 128 + hs4 * 2);
    const float4 iU = ldh4(p2 + 256 + hs4 * 2);
    const float4 f0 = ldh4(p2 + 384 + hs4 * 2);
    const float4 f1 = ldh4(p2 + 512 + hs4 * 2);

    const float4* bb = (const float4*)b_iou;
    const float4 b0 = bb[hs4], b1 = bb[64 + hs4], b2 = bb[128 + hs4];
    const float4 fb = ((const float4*)U_f_b)[hs4];

    float4 cn; float hv[4];
    #define DOLANE(c_, e_)                                                      \
    {   float csum = sigf(f0.c_ + fb.c_) * c0.c_ + sigf(f1.c_ + fb.c_) * c1.c_; \
        float cv = sigf(iI.c_ + b0.c_) * tanhf_(iU.c_ + b2.c_) + csum;          \
        cn.c_ = cv;                                                             \
        hv[e_] = sigf(iO.c_ + b1.c_) * tanhf_(cv); }
    DOLANE(x, 0) DOLANE(y, 1) DOLANE(z, 2) DOLANE(w, 3)
    #undef DOLANE

    const size_t rowoff = (size_t)bt * NTREEN * 256;
    ((float4*)(g_c + rowoff))[hs4] = cn;
    ((uint2*)(g_h + rowoff))[hs4]  = pack_h4(hv);
}

// ---------------------------------------------------------------------------
// Final classifier
// ---------------------------------------------------------------------------
__global__ __launch_bounds__(256) void final_k(
    const float* __restrict__ cls_w, const float* __restrict__ cls_b,
    float* __restrict__ out)
{
    const int b  = blockIdx.x;
    const int hs = threadIdx.x;

    const size_t o1 = (size_t)b           * NTREEN * 256 + hs;
    const size_t o2 = (size_t)(b + BATCH) * NTREEN * 256 + hs;

    float s1 = 0.f, s2 = 0.f;
    #pragma unroll 4
    for (int n = 0; n < NTREEN; n++) {
        s1 += __half2float(g_h[o1 + (size_t)n * 256]);
        s2 += __half2float(g_h[o2 + (size_t)n * 256]);
    }
    const float d = fabsf(s1 - s2) * (1.0f / (float)NTREEN);

    float v0 = d * cls_w[hs];
    float v1 = d * cls_w[256 + hs];

    #pragma unroll
    for (int off = 16; off > 0; off >>= 1) {
        v0 += __shfl_down_sync(0xffffffffu, v0, off);
        v1 += __shfl_down_sync(0xffffffffu, v1, off);
    }
    __shared__ float sm0[8], sm1[8];
    const int w = threadIdx.x >> 5, lane = threadIdx.x & 31;
    if (lane == 0) { sm0[w] = v0; sm1[w] = v1; }
    __syncthreads();
    if (threadIdx.x == 0) {
        float t0 = 0.f, t1 = 0.f;
        #pragma unroll
        for (int k = 0; k < 8; k++) { t0 += sm0[k]; t1 += sm1[k]; }
        out[b * 2 + 0] = t0 + cls_b[0];
        out[b * 2 + 1] = t1 + cls_b[1];
    }
}

// ---------------------------------------------------------------------------
// Launch
// ---------------------------------------------------------------------------
extern "C" void kernel_launch(void* const* d_in, const int* in_sizes, int n_in,
                              void* d_out, int out_size)
{
    (void)in_sizes; (void)n_in; (void)out_size;
    const int*   types1 = (const int*)  d_in[0];
    const int*   types2 = (const int*)  d_in[1];
    const float* emb    = (const float*)d_in[2];
    const float* W_iou  = (const float*)d_in[3];
    const float* U_iou  = (const float*)d_in[4];
    const float* b_iou  = (const float*)d_in[5];
    const float* U_f_w  = (const float*)d_in[6];
    const float* U_f_b  = (const float*)d_in[7];
    const float* cls_w  = (const float*)d_in[8];
    const float* cls_b  = (const float*)d_in[9];
    float* out = (float*)d_out;

    cudaFuncSetAttribute(gemm_f16<0>, cudaFuncAttributeMaxDynamicSharedMemorySize, L_SMT);
    cudaFuncSetAttribute(gemm_f16<1>, cudaFuncAttributeMaxDynamicSharedMemorySize, L_SMT);

    // 0) prep: fp16 conversions
    emb_f16<<<VOCABN, 256>>>(emb);
    wt_f16<<<768, 256>>>(W_iou);
    build_wc<<<NPRE, 256>>>(U_iou, U_f_w);

    // 1) vocab table: g_table[v] = W_iou @ emb[v], then per-vocab leaf h/c
    gemm_f16<0><<<dim3(VOCABN / 128, 6), 256, L_SMT>>>(0);
    vocab_leaf<<<VOCABN / 4, 256>>>(b_iou);

    // 2) leaves: gather + hsum (pure bandwidth)
    leaf_gather<<<16384, 256>>>(types1, types2);

    // 3) internal levels 8..1 (pipelined fp16 GEMM -> fused ew+hsum)
    for (int lvl = 8; lvl >= 1; --lvl) {
        const int base = (1 << lvl) - 1;
        gemm_f16<1><<<dim3((BTN << lvl) / 128, 10), 256, L_SMT>>>(base);
        level_ew_pair<<<64 << (lvl - 1), 256>>>(b_iou, U_f_b, base);
    }

    // 4) root level
    gemm_f16<1><<<dim3(2, 10), 256, L_SMT>>>(0);
    level_ew_root<<<64, 256>>>(b_iou, U_f_b);

    // 5) classifier
    final_k<<<BATCH, 256>>>(cls_w, cls_b, out);
}

// round 14
// speedup vs baseline: 2.0687x; 1.0397x over previous
#include <cuda_runtime.h>
#include <cuda_fp16.h>
#include <stdint.h>
#include <math.h>

// ---------------------------------------------------------------------------
// Problem constants
// ---------------------------------------------------------------------------
#define VOCABN 32000
#define BATCH  128
#define BTN    256          // 2*BATCH
#define NTREEN 1023
#define NPRE   1280         // iou(768) | f0(256) | f1(256)

// ---------------------------------------------------------------------------
// Scratch (device globals)
// ---------------------------------------------------------------------------
__device__ __align__(16) __half g_emb  [(size_t)VOCABN * 256];
__device__ __align__(16) __half g_Wt   [768 * 256];
__device__ __align__(16) __half g_Wc   [NPRE * 256];
__device__ __align__(16) __half g_table[(size_t)VOCABN * 768];
__device__ __align__(16) __half g_hleaf[(size_t)VOCABN * 256];   // leaf h per vocab (16MB, L2)
__device__ __align__(16) float  g_cleaf[(size_t)VOCABN * 256];   // leaf c per vocab (33MB, fp32)
__device__ __align__(16) __half g_h    [(size_t)BTN * NTREEN * 256];  // internal nodes only
__device__ __align__(16) __half g_c16  [(size_t)BTN * NTREEN * 256];  // internal c, fp16
__device__ __align__(16) __half g_hsum [(size_t)65536 * 256];
__device__ __align__(16) __half g_pre  [(size_t)65536 * NPRE];

// ---------------------------------------------------------------------------
// Helpers
// ---------------------------------------------------------------------------
__device__ __forceinline__ float sigf(float x)   { return 1.0f / (1.0f + __expf(-x)); }
__device__ __forceinline__ float tanhf_(float x) { return 2.0f / (1.0f + __expf(-2.0f * x)) - 1.0f; }

__device__ __forceinline__ uint32_t smem_u32(const void* p) {
    uint32_t a;
    asm("{ .reg .u64 t; cvta.to.shared.u64 t, %1; cvt.u32.u64 %0, t; }" : "=r"(a) : "l"(p));
    return a;
}
__device__ __forceinline__ float4 ldh4(const __half2* p) {
    __half2 a = p[0], b = p[1];
    return make_float4(__low2float(a), __high2float(a),
                       __low2float(b), __high2float(b));
}
__device__ __forceinline__ float4 unp_h4(uint2 u) {
    return make_float4(
        __half2float(__ushort_as_half((unsigned short)(u.x & 0xFFFF))),
        __half2float(__ushort_as_half((unsigned short)(u.x >> 16))),
        __half2float(__ushort_as_half((unsigned short)(u.y & 0xFFFF))),
        __half2float(__ushort_as_half((unsigned short)(u.y >> 16))));
}
__device__ __forceinline__ uint2 pack_h4(const float h[4]) {
    unsigned short b[4];
    #pragma unroll
    for (int e = 0; e < 4; e++) b[e] = __half_as_ushort(__float2half_rn(h[e]));
    return make_uint2(b[0] | ((unsigned)b[1] << 16), b[2] | ((unsigned)b[3] << 16));
}

// ---------------------------------------------------------------------------
// Baseline-PTX tensor ops + cp.async
// ---------------------------------------------------------------------------
__device__ __forceinline__ void ldm_x4(uint32_t r[4], uint32_t addr) {
    asm volatile("ldmatrix.sync.aligned.m8n8.x4.shared.b16 {%0,%1,%2,%3}, [%4];"
        : "=r"(r[0]), "=r"(r[1]), "=r"(r[2]), "=r"(r[3]) : "r"(addr));
}
__device__ __forceinline__ void ldm_x2(uint32_t r[2], uint32_t addr) {
    asm volatile("ldmatrix.sync.aligned.m8n8.x2.shared.b16 {%0,%1}, [%2];"
        : "=r"(r[0]), "=r"(r[1]) : "r"(addr));
}
__device__ __forceinline__ void mma_f16(float c[4], const uint32_t a[4], const uint32_t b[2]) {
    asm volatile("mma.sync.aligned.m16n8k16.row.col.f32.f16.f16.f32 "
        "{%0,%1,%2,%3}, {%4,%5,%6,%7}, {%8,%9}, {%0,%1,%2,%3};"
        : "+f"(c[0]), "+f"(c[1]), "+f"(c[2]), "+f"(c[3])
        : "r"(a[0]), "r"(a[1]), "r"(a[2]), "r"(a[3]), "r"(b[0]), "r"(b[1]));
}
#define CP16(dst, src) asm volatile("cp.async.cg.shared.global [%0], [%1], 16;" :: "r"(dst), "l"(src))
#define CP_COMMIT()    asm volatile("cp.async.commit_group;" ::: "memory")
#define CP_WAIT1()     asm volatile("cp.async.wait_group 1;" ::: "memory")
#define CP_WAIT0()     asm volatile("cp.async.wait_group 0;" ::: "memory")

// ---------------------------------------------------------------------------
// Prep kernels
// ---------------------------------------------------------------------------
__global__ __launch_bounds__(256) void emb_f16(const float* __restrict__ src)
{
    const int idx = blockIdx.x * 256 + threadIdx.x;
    g_emb[idx] = __float2half_rn(src[idx]);
}
__global__ __launch_bounds__(256) void wt_f16(const float* __restrict__ src)
{
    const int idx = blockIdx.x * 256 + threadIdx.x;
    g_Wt[idx] = __float2half_rn(src[idx]);
}
__global__ __launch_bounds__(256) void build_wc(
    const float* __restrict__ U_iou, const float* __restrict__ U_f_w)
{
    const int idx = blockIdx.x * 256 + threadIdx.x;
    const int n = idx >> 8, k = idx & 255;
    const float v = (n < 768) ? U_iou[n * 256 + k]
                              : U_f_w[((n - 768) & 255) * 256 + k];
    g_Wc[idx] = __float2half_rn(v);
}

// ---------------------------------------------------------------------------
// Double-buffered single-pass fp16 GEMM.  C[M,N](fp16) = A[M,256] @ B[N,256]^T
// CTA tile 128x128, K = 4 chunks of 64, 2 stages x 32KB = 64KB, 2 CTA/SM.
// MODE 0 (table): A = g_emb, B = g_Wt, C = g_table (Nc=768, 6 n-tiles)
// MODE 1 (level): tiles 0-5: A = hsum | 6,7: child0 | 8,9: child1; C = g_pre
//   LEAF=1 (level 8): child A rows gathered from g_hleaf via types.
// ---------------------------------------------------------------------------
#define SM_A  0u
#define SM_B  16384u
#define STGS  32768u
#define L_SMT 65536

template<int MODE, int LEAF>
__global__ __launch_bounds__(256, 2) void gemm_f16(
    int base, const int* __restrict__ types1, const int* __restrict__ types2)
{
    extern __shared__ char smem[];
    const uint32_t sb = smem_u32(smem);
    const int tid = threadIdx.x, wid = tid >> 5, lane = tid & 31;
    const int bm = blockIdx.x * 128;
    const int tile = blockIdx.y;
    const int bn = tile * 128;
    const int Nc = (MODE == 0) ? 768 : NPRE;

    // A source (fp16 plane)
    const __half* a;
    {
        const int r = bm + (tid >> 1);
        if (MODE == 0) {
            a = g_emb + (size_t)r * 256;
        } else if (tile < 6) {
            a = g_hsum + (size_t)r * 256;
        } else {
            const int s = (tile - 6) >> 1;
            const int j = r >> 8, bt = r & 255;
            const int child = 2 * (base + j) + 1 + s;
            if (LEAF) {
                const int* ty = (bt < BATCH) ? types1 + bt * NTREEN
                                             : types2 + (bt - BATCH) * NTREEN;
                a = g_hleaf + (size_t)ty[child] * 256;
            } else {
                a = g_h + ((size_t)bt * NTREEN + child) * 256;
            }
        }
        a += (tid & 1) * 32;
    }
    const __half* b = ((MODE == 0) ? g_Wt : g_Wc)
                      + (size_t)(bn + (tid >> 1)) * 256 + (tid & 1) * 32;

    const uint32_t rowoff = (uint32_t)(tid >> 1) * 128u;
    const uint32_t rxor   = (uint32_t)(((tid >> 1) & 7) << 4);

    #define LOADC(s, k0) do {                                                  \
        const uint32_t st_ = sb + (uint32_t)(s) * STGS;                        \
        _Pragma("unroll")                                                      \
        for (int j = 0; j < 4; j++) {                                          \
            const uint32_t xo = (uint32_t)((tid & 1) * 64 + j * 16) ^ rxor;    \
            const uint32_t d = rowoff + xo;                                    \
            CP16(st_ + SM_A + d, a + (k0) + j * 8);                            \
            CP16(st_ + SM_B + d, b + (k0) + j * 8);                            \
        }                                                                      \
    } while (0)

    const int wm = (wid & 1) * 64;
    const int wn = (wid >> 1) * 32;
    float acc[4][4][4] = {};

    LOADC(0, 0);
    CP_COMMIT();

    #pragma unroll 1
    for (int kc = 0; kc < 4; kc++) {
        if (kc < 3) {
            LOADC((kc + 1) & 1, (kc + 1) * 64);
            CP_COMMIT();
            CP_WAIT1();
        } else {
            CP_WAIT0();
        }
        __syncthreads();

        const uint32_t st = sb + (uint32_t)(kc & 1) * STGS;
        #pragma unroll
        for (int kg = 0; kg < 4; kg++) {
            uint32_t bf[4][2];
            #pragma unroll
            for (int nf = 0; nf < 4; nf++) {
                const uint32_t nrow = (uint32_t)(wn + nf * 8 + (lane & 7));
                const uint32_t x = (uint32_t)(kg * 32 + ((lane >> 3) & 1) * 16);
                const uint32_t sw = nrow * 128u + (x ^ ((nrow & 7u) << 4));
                ldm_x2(bf[nf], st + SM_B + sw);
            }
            #pragma unroll
            for (int mf = 0; mf < 4; mf++) {
                const uint32_t mrow = (uint32_t)(wm + mf * 16 + (lane & 15));
                const uint32_t x = (uint32_t)(kg * 32 + (lane >> 4) * 16);
                const uint32_t sw = mrow * 128u + (x ^ ((mrow & 7u) << 4));
                uint32_t a4[4];
                ldm_x4(a4, st + SM_A + sw);
                #pragma unroll
                for (int nf = 0; nf < 4; nf++)
                    mma_f16(acc[mf][nf], a4, bf[nf]);
            }
        }
        __syncthreads();
    }
    #undef LOADC

    __half* __restrict__ C = (MODE == 0) ? g_table : g_pre;
    #pragma unroll
    for (int mf = 0; mf < 4; mf++) {
        const int row = bm + wm + mf * 16 + (lane >> 2);
        #pragma unroll
        for (int nf = 0; nf < 4; nf++) {
            const int col = bn + wn + nf * 8 + (lane & 3) * 2;
            *(__half2*)&C[(size_t)row * Nc + col] =
                __floats2half2_rn(acc[mf][nf][0], acc[mf][nf][1]);
            *(__half2*)&C[(size_t)(row + 8) * Nc + col] =
                __floats2half2_rn(acc[mf][nf][2], acc[mf][nf][3]);
        }
    }
}

// ---------------------------------------------------------------------------
// Vocab leaf precompute: per-vocab leaf h (fp16) and c (fp32).
// ---------------------------------------------------------------------------
__global__ __launch_bounds__(256) void vocab_leaf(const float* __restrict__ b_iou)
{
    const int t   = blockIdx.x * 256 + threadIdx.x;
    const int hs4 = t & 63;
    const int v   = t >> 6;

    const float4* bb = (const float4*)b_iou;
    const float4 b0 = bb[hs4], b1 = bb[64 + hs4], b2 = bb[128 + hs4];

    const __half2* t2 = (const __half2*)(g_table + (size_t)v * 768);
    const float4 i4 = ldh4(t2 + hs4 * 2);
    const float4 o4 = ldh4(t2 + 128 + hs4 * 2);
    const float4 u4 = ldh4(t2 + 256 + hs4 * 2);

    float4 cn; float hv[4];
    #define DOLANE(c_, e_)                                       \
    {   float cv = sigf(i4.c_ + b0.c_) * tanhf_(u4.c_ + b2.c_);  \
        cn.c_ = cv;                                              \
        hv[e_] = sigf(o4.c_ + b1.c_) * tanhf_(cv); }
    DOLANE(x, 0) DOLANE(y, 1) DOLANE(z, 2) DOLANE(w, 3)
    #undef DOLANE

    ((float4*)(g_cleaf + (size_t)v * 256))[hs4] = cn;
    ((uint2*)(g_hleaf + (size_t)v * 256))[hs4]  = pack_h4(hv);
}

// ---------------------------------------------------------------------------
// Leaf hsum only: hsum[pair] = hleaf[types[left]] + hleaf[types[right]].
// ---------------------------------------------------------------------------
__global__ __launch_bounds__(256) void leaf_hsum(
    const int* __restrict__ types1, const int* __restrict__ types2)
{
    const int tid = blockIdx.x * 256 + threadIdx.x;
    const int hs4 = tid & 63;
    const int q   = tid >> 6;
    const int bt  = q & 255;
    const int tp  = q >> 8;              // pair 0..255

    const int* ty = (bt < BATCH) ? types1 + bt * NTREEN
                                 : types2 + (bt - BATCH) * NTREEN;
    const int v0 = ty[511 + 2 * tp];
    const int v1 = ty[511 + 2 * tp + 1];

    const float4 h0 = unp_h4(((const uint2*)(g_hleaf + (size_t)v0 * 256))[hs4]);
    const float4 h1 = unp_h4(((const uint2*)(g_hleaf + (size_t)v1 * 256))[hs4]);

    float hs[4] = { h0.x + h1.x, h0.y + h1.y, h0.z + h1.z, h0.w + h1.w };
    ((uint2*)(g_hsum + (size_t)(tp * 256 + bt) * 256))[hs4] = pack_h4(hs);
}

// ---------------------------------------------------------------------------
// Internal-level elementwise, fused sibling pair + hsum.
// LEAF=1 (level 8): children c gathered from g_cleaf via types (fp32).
// LEAF=0: children c from g_c16 (fp16).
// ---------------------------------------------------------------------------
template<int LEAF>
__global__ __launch_bounds__(256) void level_ew_pair(
    const float* __restrict__ b_iou, const float* __restrict__ U_f_b, int cbase,
    const int* __restrict__ types1, const int* __restrict__ types2)
{
    const int tid = blockIdx.x * 256 + threadIdx.x;
    const int hs4 = tid & 63;
    const int q   = tid >> 6;
    const int bt  = q & 255;
    const int tp  = q >> 8;

    const float4* bb = (const float4*)b_iou;
    const float4 b0 = bb[hs4], b1 = bb[64 + hs4], b2 = bb[128 + hs4];
    const float4 fb = ((const float4*)U_f_b)[hs4];

    const int* ty = (bt < BATCH) ? types1 + bt * NTREEN
                                 : types2 + (bt - BATCH) * NTREEN;

    float hsum[4] = {0.f, 0.f, 0.f, 0.f};
    #pragma unroll
    for (int s = 0; s < 2; s++) {
        const int node = cbase + 2 * tp + s;
        const int i    = (2 * tp + s) * 256 + bt;

        float4 c0, c1;
        if (LEAF) {
            const int v0 = ty[2 * node + 1];
            const int v1 = ty[2 * node + 2];
            c0 = ((const float4*)(g_cleaf + (size_t)v0 * 256))[hs4];
            c1 = ((const float4*)(g_cleaf + (size_t)v1 * 256))[hs4];
        } else {
            const size_t rc0 = ((size_t)bt * NTREEN + 2 * node + 1) * 256;
            c0 = unp_h4(((const uint2*)(g_c16 + rc0))[hs4]);
            c1 = unp_h4(((const uint2*)(g_c16 + rc0 + 256))[hs4]);
        }

        const __half2* p2 = (const __half2*)(g_pre + (size_t)i * NPRE);
        const float4 iI = ldh4(p2 + hs4 * 2);
        const float4 iO = ldh4(p2 + 128 + hs4 * 2);
        const float4 iU = ldh4(p2 + 256 + hs4 * 2);
        const float4 f0 = ldh4(p2 + 384 + hs4 * 2);
        const float4 f1 = ldh4(p2 + 512 + hs4 * 2);

        float cnv[4]; float hv[4];
        #define DOLANE(c_, e_)                                                      \
        {   float csum = sigf(f0.c_ + fb.c_) * c0.c_ + sigf(f1.c_ + fb.c_) * c1.c_; \
            float cv = sigf(iI.c_ + b0.c_) * tanhf_(iU.c_ + b2.c_) + csum;          \
            cnv[e_] = cv;                                                           \
            hv[e_] = sigf(iO.c_ + b1.c_) * tanhf_(cv);                              \
            hsum[e_] += hv[e_]; }
        DOLANE(x, 0) DOLANE(y, 1) DOLANE(z, 2) DOLANE(w, 3)
        #undef DOLANE

        const size_t rowoff = ((size_t)bt * NTREEN + node) * 256;
        ((uint2*)(g_c16 + rowoff))[hs4] = pack_h4(cnv);
        ((uint2*)(g_h + rowoff))[hs4]   = pack_h4(hv);
    }
    ((uint2*)(g_hsum + (size_t)(tp * 256 + bt) * 256))[hs4] = pack_h4(hsum);
}

// ---------------------------------------------------------------------------
// Root elementwise (node 0, no hsum)
// ---------------------------------------------------------------------------
__global__ __launch_bounds__(256) void level_ew_root(
    const float* __restrict__ b_iou, const float* __restrict__ U_f_b)
{
    const int tid = blockIdx.x * 256 + threadIdx.x;
    const int hs4 = tid & 63;
    const int bt  = tid >> 6;

    const size_t rc0 = ((size_t)bt * NTREEN + 1) * 256;
    const float4 c0 = unp_h4(((const uint2*)(g_c16 + rc0))[hs4]);
    const float4 c1 = unp_h4(((const uint2*)(g_c16 + rc0 + 256))[hs4]);

    const __half2* p2 = (const __half2*)(g_pre + (size_t)bt * NPRE);
    const float4 iI = ldh4(p2 + hs4 * 2);
    const float4 iO = ldh4(p2 + 128 + hs4 * 2);
    const float4 iU = ldh4(p2 + 256 + hs4 * 2);
    const float4 f0 = ldh4(p2 + 384 + hs4 * 2);
    const float4 f1 = ldh4(p2 + 512 + hs4 * 2);

    const float4* bb = (const float4*)b_iou;
    const float4 b0 = bb[hs4], b1 = bb[64 + hs4], b2 = bb[128 + hs4];
    const float4 fb = ((const float4*)U_f_b)[hs4];

    float cnv[4]; float hv[4];
    #define DOLANE(c_, e_)                                                      \
    {   float csum = sigf(f0.c_ + fb.c_) * c0.c_ + sigf(f1.c_ + fb.c_) * c1.c_; \
        float cv = sigf(iI.c_ + b0.c_) * tanhf_(iU.c_ + b2.c_) + csum;          \
        cnv[e_] = cv;                                                           \
        hv[e_] = sigf(iO.c_ + b1.c_) * tanhf_(cv); }
    DOLANE(x, 0) DOLANE(y, 1) DOLANE(z, 2) DOLANE(w, 3)
    #undef DOLANE

    const size_t rowoff = (size_t)bt * NTREEN * 256;
    ((uint2*)(g_c16 + rowoff))[hs4] = pack_h4(cnv);
    ((uint2*)(g_h + rowoff))[hs4]   = pack_h4(hv);
}

// ---------------------------------------------------------------------------
// Final classifier: internal nodes from g_h, leaves gathered via types.
// ---------------------------------------------------------------------------
__global__ __launch_bounds__(256) void final_k(
    const int* __restrict__ types1, const int* __restrict__ types2,
    const float* __restrict__ cls_w, const float* __restrict__ cls_b,
    float* __restrict__ out)
{
    const int b  = blockIdx.x;
    const int hs = threadIdx.x;

    const size_t o1 = (size_t)b           * NTREEN * 256 + hs;
    const size_t o2 = (size_t)(b + BATCH) * NTREEN * 256 + hs;
    const int* ty1 = types1 + b * NTREEN;
    const int* ty2 = types2 + b * NTREEN;

    float s1 = 0.f, s2 = 0.f;
    #pragma unroll 4
    for (int n = 0; n < 511; n++) {
        s1 += __half2float(g_h[o1 + (size_t)n * 256]);
        s2 += __half2float(g_h[o2 + (size_t)n * 256]);
    }
    #pragma unroll 4
    for (int n = 511; n < NTREEN; n++) {
        s1 += __half2float(g_hleaf[(size_t)ty1[n] * 256 + hs]);
        s2 += __half2float(g_hleaf[(size_t)ty2[n] * 256 + hs]);
    }
    const float d = fabsf(s1 - s2) * (1.0f / (float)NTREEN);

    float v0 = d * cls_w[hs];
    float v1 = d * cls_w[256 + hs];

    #pragma unroll
    for (int off = 16; off > 0; off >>= 1) {
        v0 += __shfl_down_sync(0xffffffffu, v0, off);
        v1 += __shfl_down_sync(0xffffffffu, v1, off);
    }
    __shared__ float sm0[8], sm1[8];
    const int w = threadIdx.x >> 5, lane = threadIdx.x & 31;
    if (lane == 0) { sm0[w] = v0; sm1[w] = v1; }
    __syncthreads();
    if (threadIdx.x == 0) {
        float t0 = 0.f, t1 = 0.f;
        #pragma unroll
        for (int k = 0; k < 8; k++) { t0 += sm0[k]; t1 += sm1[k]; }
        out[b * 2 + 0] = t0 + cls_b[0];
        out[b * 2 + 1] = t1 + cls_b[1];
    }
}

// ---------------------------------------------------------------------------
// Launch
// ---------------------------------------------------------------------------
extern "C" void kernel_launch(void* const* d_in, const int* in_sizes, int n_in,
                              void* d_out, int out_size)
{
    (void)in_sizes; (void)n_in; (void)out_size;
    const int*   types1 = (const int*)  d_in[0];
    const int*   types2 = (const int*)  d_in[1];
    const float* emb    = (const float*)d_in[2];
    const float* W_iou  = (const float*)d_in[3];
    const float* U_iou  = (const float*)d_in[4];
    const float* b_iou  = (const float*)d_in[5];
    const float* U_f_w  = (const float*)d_in[6];
    const float* U_f_b  = (const float*)d_in[7];
    const float* cls_w  = (const float*)d_in[8];
    const float* cls_b  = (const float*)d_in[9];
    float* out = (float*)d_out;

    cudaFuncSetAttribute(gemm_f16<0,0>, cudaFuncAttributeMaxDynamicSharedMemorySize, L_SMT);
    cudaFuncSetAttribute(gemm_f16<1,0>, cudaFuncAttributeMaxDynamicSharedMemorySize, L_SMT);
    cudaFuncSetAttribute(gemm_f16<1,1>, cudaFuncAttributeMaxDynamicSharedMemorySize, L_SMT);

    // 0) prep: fp16 conversions
    emb_f16<<<VOCABN, 256>>>(emb);
    wt_f16<<<768, 256>>>(W_iou);
    build_wc<<<NPRE, 256>>>(U_iou, U_f_w);

    // 1) vocab table + per-vocab leaf h/c
    gemm_f16<0,0><<<dim3(VOCABN / 128, 6), 256, L_SMT>>>(0, nullptr, nullptr);
    vocab_leaf<<<VOCABN / 4, 256>>>(b_iou);

    // 2) leaf hsum (only materialization needed for leaves)
    leaf_hsum<<<16384, 256>>>(types1, types2);

    // 3) level 8 (children = leaves, gathered via types)
    {
        const int base = 255;
        gemm_f16<1,1><<<dim3((BTN << 8) / 128, 10), 256, L_SMT>>>(base, types1, types2);
        level_ew_pair<1><<<64 << 7, 256>>>(b_iou, U_f_b, base, types1, types2);
    }

    // 4) internal levels 7..1
    for (int lvl = 7; lvl >= 1; --lvl) {
        const int base = (1 << lvl) - 1;
        gemm_f16<1,0><<<dim3((BTN << lvl) / 128, 10), 256, L_SMT>>>(base, nullptr, nullptr);
        level_ew_pair<0><<<64 << (lvl - 1), 256>>>(b_iou, U_f_b, base, types1, types2);
    }

    // 5) root level
    gemm_f16<1,0><<<dim3(2, 10), 256, L_SMT>>>(0, nullptr, nullptr);
    level_ew_root<<<64, 256>>>(b_iou, U_f_b);

    // 6) classifier
    final_k<<<BATCH, 256>>>(types1, types2, cls_w, cls_b, out);
}